// round 5
// baseline (speedup 1.0000x reference)
#include <cuda_runtime.h>
#include <cuda_bf16.h>
#include <cuda_fp8.h>
#include <cstdint>

#define L_TOK  8192
#define C_DIM  1024
#define INNER  1024
#define H_NUM  16
#define D_DIM  64
#define NSHIFT 16

#define BM 128
#define BN 128
#define NSTAGE 3
#define STAGE_BYTES 65536      // Ahi16K | A8 16K | Bhi16K | B8 16K
#define SMEM_TOTAL (NSTAGE * STAGE_BYTES)
#define CORR_SCALE 512.0f
#define CORR_INV   0.001953125f

// ---------------- scratch ----------------------------------------------------
// bf16 hi: row-major [row][1024] (2048 B/row)
// fp8 pack: [row][kc 0..15][128B = hi8[64] | lo8[64]]  (2048 B/row)
__device__ __align__(256) unsigned short g_xhi [L_TOK * 1024];
__device__ __align__(256) unsigned char  g_x8  [L_TOK * 2048];
__device__ __align__(256) unsigned short g_ahi [L_TOK * 1024];
__device__ __align__(256) unsigned char  g_a8  [L_TOK * 2048];
__device__ __align__(256) unsigned short g_wqkvhi[3072 * 1024];
__device__ __align__(256) unsigned char  g_wqkv8 [3072 * 2048];
__device__ __align__(256) unsigned short g_wohi[1024 * 1024];
__device__ __align__(256) unsigned char  g_wo8 [1024 * 2048];
__device__ float g_bqkv[3072];
__device__ float g_q[L_TOK * INNER];
__device__ float g_k[L_TOK * INNER];
__device__ float g_v[L_TOK * INNER];
__device__ float g_ssq_q[L_TOK];
__device__ float g_ssq_k[L_TOK];

__constant__ int c_shift[NSHIFT] = {1,-1,2,-2,4,-4,8,-8,16,-16,32,-32, 1,-1,2,-2};

// ---------------- helpers ---------------------------------------------------
__device__ __forceinline__ uint32_t smem_u32(const void* p){
    uint32_t a;
    asm("{ .reg .u64 t; cvta.to.shared.u64 t, %1; cvt.u32.u64 %0, t; }" : "=r"(a) : "l"(p));
    return a;
}
// pack pair -> bf16 hi (u32), fp8x2 of value (h8), fp8x2 of scaled residual (l8)
__device__ __forceinline__ void pack3(float a, float b, uint32_t& hbf,
                                      uint16_t& h8, uint16_t& l8){
    __nv_bfloat16 h0 = __float2bfloat16(a), h1 = __float2bfloat16(b);
    hbf = (uint32_t)__bfloat16_as_ushort(h0) | ((uint32_t)__bfloat16_as_ushort(h1) << 16);
    float r0 = (a - __bfloat162float(h0)) * CORR_SCALE;
    float r1 = (b - __bfloat162float(h1)) * CORR_SCALE;
    __nv_fp8x2_e4m3 p8(make_float2(a, b));
    __nv_fp8x2_e4m3 q8(make_float2(r0, r1));
    h8 = *(uint16_t*)&p8;
    l8 = *(uint16_t*)&q8;
}
__device__ __forceinline__ void cp16(uint32_t s, const void* g){
    asm volatile("cp.async.cg.shared.global [%0], [%1], 16;" :: "r"(s), "l"(g) : "memory");
}
__device__ __forceinline__ void ldsm_x4(uint32_t* r, uint32_t addr){
    asm volatile("ldmatrix.sync.aligned.m8n8.x4.shared.b16 {%0,%1,%2,%3}, [%4];"
        : "=r"(r[0]), "=r"(r[1]), "=r"(r[2]), "=r"(r[3]) : "r"(addr));
}
__device__ __forceinline__ void mma_bf16(float* d, const uint32_t* a, uint32_t b0, uint32_t b1){
    asm volatile("mma.sync.aligned.m16n8k16.row.col.f32.bf16.bf16.f32 "
        "{%0,%1,%2,%3}, {%4,%5,%6,%7}, {%8,%9}, {%0,%1,%2,%3};"
        : "+f"(d[0]), "+f"(d[1]), "+f"(d[2]), "+f"(d[3])
        : "r"(a[0]), "r"(a[1]), "r"(a[2]), "r"(a[3]), "r"(b0), "r"(b1));
}
__device__ __forceinline__ void mma_fp8(float* d, const uint32_t* a, uint32_t b0, uint32_t b1){
    asm volatile("mma.sync.aligned.m16n8k32.row.col.f32.e4m3.e4m3.f32 "
        "{%0,%1,%2,%3}, {%4,%5,%6,%7}, {%8,%9}, {%0,%1,%2,%3};"
        : "+f"(d[0]), "+f"(d[1]), "+f"(d[2]), "+f"(d[3])
        : "r"(a[0]), "r"(a[1]), "r"(a[2]), "r"(a[3]), "r"(b0), "r"(b1));
}

// ---------------- converters -------------------------------------------------
// x fp32 [8192][1024] -> bf16 hi + fp8 pack. 8 elems/thread.
__global__ __launch_bounds__(256)
void conv_x(const float* __restrict__ x, unsigned short* __restrict__ hi,
            unsigned char* __restrict__ p8)
{
    int gid = blockIdx.x * 256 + threadIdx.x;
    int e0 = gid * 8;
    int row = e0 >> 10, k = e0 & 1023;
    float4 f0 = *(const float4*)&x[e0];
    float4 f1 = *(const float4*)&x[e0 + 4];
    uint32_t hb[4]; uint16_t h8[4], l8[4];
    pack3(f0.x, f0.y, hb[0], h8[0], l8[0]);
    pack3(f0.z, f0.w, hb[1], h8[1], l8[1]);
    pack3(f1.x, f1.y, hb[2], h8[2], l8[2]);
    pack3(f1.z, f1.w, hb[3], h8[3], l8[3]);
    *(uint4*)&hi[e0] = make_uint4(hb[0], hb[1], hb[2], hb[3]);
    unsigned long long hq = (unsigned long long)h8[0] | ((unsigned long long)h8[1] << 16)
                          | ((unsigned long long)h8[2] << 32) | ((unsigned long long)h8[3] << 48);
    unsigned long long lq = (unsigned long long)l8[0] | ((unsigned long long)l8[1] << 16)
                          | ((unsigned long long)l8[2] << 32) | ((unsigned long long)l8[3] << 48);
    size_t base = (size_t)row * 2048 + (k >> 6) * 128 + (k & 63);
    *(unsigned long long*)&p8[base]      = hq;
    *(unsigned long long*)&p8[base + 64] = lq;
}

// W [K=1024][N=1024] fp32 -> transposed [n][k] bf16 hi + fp8 pack
__global__ __launch_bounds__(256)
void conv_w(const float* __restrict__ W, unsigned short* __restrict__ hi,
            unsigned char* __restrict__ p8, int n_off)
{
    __shared__ float tile[32][33];
    const int t = threadIdx.x;
    const int tx = t & 31, ty = t >> 5;
    const int k0 = blockIdx.x * 32, n0 = blockIdx.y * 32;
    #pragma unroll
    for (int r = 0; r < 4; r++) {
        int kl = ty + r * 8;
        tile[kl][tx] = W[(size_t)(k0 + kl) * 1024 + n0 + tx];
    }
    __syncthreads();
    int j  = t >> 3;            // n row 0..31
    int ku = (t & 7) * 4;       // k elems 0..28
    uint32_t hb0, hb1; uint16_t h0, h1, l0, l1;
    pack3(tile[ku + 0][j], tile[ku + 1][j], hb0, h0, l0);
    pack3(tile[ku + 2][j], tile[ku + 3][j], hb1, h1, l1);
    int n = n_off + n0 + j;
    int k = k0 + ku;
    *(uint2*)&hi[(size_t)n * 1024 + k] = make_uint2(hb0, hb1);
    size_t base = (size_t)n * 2048 + (k >> 6) * 128 + (k & 63);
    *(uint32_t*)&p8[base]      = (uint32_t)h0 | ((uint32_t)h1 << 16);
    *(uint32_t*)&p8[base + 64] = (uint32_t)l0 | ((uint32_t)l1 << 16);
}

// bias concat + zero sumsq accumulators
__global__ void init_misc(const float* bq, const float* bk, const float* bv,
                          float* bqkv, float* ssq_q, float* ssq_k)
{
    int i = blockIdx.x * 256 + threadIdx.x;
    if (i < 1024)       bqkv[i] = bq[i];
    else if (i < 2048)  bqkv[i] = bk[i - 1024];
    else if (i < 3072)  bqkv[i] = bv[i - 2048];
    else {
        int j = i - 3072;
        if (j < L_TOK)            ssq_q[j] = 0.f;
        else if (j < 2 * L_TOK)   ssq_k[j - L_TOK] = 0.f;
    }
}

// ---------------- bf16-main + fp8-correction MMA GEMM ------------------------
// mode 0: Ntot=3072 -> q/k/v (+ per-row sumsq for q,k).  mode 1: single out.
__global__ __launch_bounds__(256, 1)
void gemm_mma(const unsigned short* __restrict__ Ahi, const unsigned char* __restrict__ A8,
              const unsigned short* __restrict__ Bhi, const unsigned char* __restrict__ B8,
              const float* __restrict__ bias,
              float* __restrict__ out0, float* __restrict__ out1, float* __restrict__ out2,
              float* __restrict__ ssq_q, float* __restrict__ ssq_k, int mode)
{
    extern __shared__ __align__(128) unsigned char smem[];
    const uint32_t sbase = smem_u32(smem);
    const int tid  = threadIdx.x;
    const int lane = tid & 31;
    const int wid  = tid >> 5;
    const int wm   = wid >> 2;
    const int wn   = wid & 3;
    const int mblk = blockIdx.y * BM;
    const int nblk = blockIdx.x * BN;

    const unsigned char* bases[4] = {
        (const unsigned char*)Ahi, A8, (const unsigned char*)Bhi, B8 };
    const int rb[4] = { mblk, mblk, nblk, nblk };

    auto load_stage = [&](int kc, int st){
        const uint32_t sb = sbase + st * STAGE_BYTES;
        #pragma unroll
        for (int mat = 0; mat < 4; mat++) {
            #pragma unroll
            for (int j = 0; j < 4; j++) {
                int id  = tid + j * 256;
                int row = id >> 3;
                int c   = id & 7;
                uint32_t soff = mat * 16384 + row * 128 + ((c ^ (row & 7)) << 4);
                const void* g = bases[mat] + (size_t)(rb[mat] + row) * 2048 + kc * 128 + c * 16;
                cp16(sb + soff, g);
            }
        }
        asm volatile("cp.async.commit_group;" ::: "memory");
    };

    float acc[4][4][4];
    float accc[4][4][4];
    #pragma unroll
    for (int i = 0; i < 4; i++)
        #pragma unroll
        for (int j = 0; j < 4; j++)
            #pragma unroll
            for (int e = 0; e < 4; e++) { acc[i][j][e] = 0.f; accc[i][j][e] = 0.f; }

    load_stage(0, 0);
    load_stage(1, 1);

    for (int kc = 0; kc < 16; kc++) {
        if (kc < 15) asm volatile("cp.async.wait_group 1;" ::: "memory");
        else         asm volatile("cp.async.wait_group 0;" ::: "memory");
        __syncthreads();

        const uint32_t sb  = sbase + (kc % NSTAGE) * STAGE_BYTES;
        const uint32_t sAh = sb, sA8 = sb + 16384, sBh = sb + 32768, sB8 = sb + 49152;

        // main term: bf16 k16, 4 s-steps
        #pragma unroll
        for (int s = 0; s < 4; s++) {
            uint32_t ah[4][4];
            int r = wm * 64 + (lane & 15);
            int c = 2 * s + (lane >> 4);
            #pragma unroll
            for (int mt = 0; mt < 4; mt++) {
                int rr = r + mt * 16;
                ldsm_x4(ah[mt], sAh + rr * 128 + ((c ^ (rr & 7)) << 4));
            }
            uint32_t bh[4][2];
            int rB = wn * 32 + (lane & 15);
            #pragma unroll
            for (int p = 0; p < 2; p++) {
                int rr = rB + p * 16;
                uint32_t t4[4];
                ldsm_x4(t4, sBh + rr * 128 + ((c ^ (rr & 7)) << 4));
                bh[p*2+0][0] = t4[0]; bh[p*2+0][1] = t4[2];
                bh[p*2+1][0] = t4[1]; bh[p*2+1][1] = t4[3];
            }
            #pragma unroll
            for (int mt = 0; mt < 4; mt++)
                #pragma unroll
                for (int nt = 0; nt < 4; nt++)
                    mma_bf16(acc[mt][nt], ah[mt], bh[nt][0], bh[nt][1]);
        }

        // corrections: fp8 k32, 2 s8-steps: Ahi8*Blo8 + Alo8*Bhi8
        #pragma unroll
        for (int s8 = 0; s8 < 2; s8++) {
            int uh = s8 * 2 + (lane >> 4);
            int ul = uh + 4;
            uint32_t a8h[4][4], a8l[4][4];
            int r = wm * 64 + (lane & 15);
            #pragma unroll
            for (int mt = 0; mt < 4; mt++) {
                int rr = r + mt * 16;
                ldsm_x4(a8h[mt], sA8 + rr * 128 + ((uh ^ (rr & 7)) << 4));
                ldsm_x4(a8l[mt], sA8 + rr * 128 + ((ul ^ (rr & 7)) << 4));
            }
            uint32_t b8h[4][2], b8l[4][2];
            int rB = wn * 32 + (lane & 15);
            #pragma unroll
            for (int p = 0; p < 2; p++) {
                int rr = rB + p * 16;
                uint32_t t4[4];
                ldsm_x4(t4, sB8 + rr * 128 + ((uh ^ (rr & 7)) << 4));
                b8h[p*2+0][0] = t4[0]; b8h[p*2+0][1] = t4[2];
                b8h[p*2+1][0] = t4[1]; b8h[p*2+1][1] = t4[3];
                ldsm_x4(t4, sB8 + rr * 128 + ((ul ^ (rr & 7)) << 4));
                b8l[p*2+0][0] = t4[0]; b8l[p*2+0][1] = t4[2];
                b8l[p*2+1][0] = t4[1]; b8l[p*2+1][1] = t4[3];
            }
            #pragma unroll
            for (int mt = 0; mt < 4; mt++)
                #pragma unroll
                for (int nt = 0; nt < 4; nt++) {
                    mma_fp8(accc[mt][nt], a8h[mt], b8l[nt][0], b8l[nt][1]);
                    mma_fp8(accc[mt][nt], a8l[mt], b8h[nt][0], b8h[nt][1]);
                }
        }

        __syncthreads();
        if (kc + 2 < 16) load_stage(kc + 2, (kc + 2) % NSTAGE);
    }

    // epilogue (+ optional per-row sumsq for q,k)
    const int bi = nblk >> 10;                 // 0:q 1:k 2:v (mode 0)
    float rsum[4][2];
    #pragma unroll
    for (int mt = 0; mt < 4; mt++) { rsum[mt][0] = 0.f; rsum[mt][1] = 0.f; }

    #pragma unroll
    for (int mt = 0; mt < 4; mt++) {
        #pragma unroll
        for (int nt = 0; nt < 4; nt++) {
            int m0  = mblk + wm * 64 + mt * 16 + (lane >> 2);
            int n_g = nblk + wn * 32 + nt * 8 + 2 * (lane & 3);
            float* dst; int nl;
            if (mode == 0) { dst = (bi == 0) ? out0 : (bi == 1) ? out1 : out2; nl = n_g & 1023; }
            else           { dst = out0; nl = n_g; }
            float b0 = bias[n_g], b1 = bias[n_g + 1];
            float vx0 = acc[mt][nt][0] + CORR_INV * accc[mt][nt][0] + b0;
            float vy0 = acc[mt][nt][1] + CORR_INV * accc[mt][nt][1] + b1;
            float vx1 = acc[mt][nt][2] + CORR_INV * accc[mt][nt][2] + b0;
            float vy1 = acc[mt][nt][3] + CORR_INV * accc[mt][nt][3] + b1;
            *(float2*)&dst[(size_t)m0 * 1024 + nl]       = make_float2(vx0, vy0);
            *(float2*)&dst[(size_t)(m0 + 8) * 1024 + nl] = make_float2(vx1, vy1);
            if (mode == 0 && bi < 2) {
                rsum[mt][0] += vx0 * vx0 + vy0 * vy0;
                rsum[mt][1] += vx1 * vx1 + vy1 * vy1;
            }
        }
    }
    if (mode == 0 && bi < 2) {
        float* ssq = (bi == 0) ? ssq_q : ssq_k;
        #pragma unroll
        for (int mt = 0; mt < 4; mt++) {
            #pragma unroll
            for (int h = 0; h < 2; h++) {
                float v = rsum[mt][h];
                v += __shfl_xor_sync(0xffffffffu, v, 1);
                v += __shfl_xor_sync(0xffffffffu, v, 2);
                if ((lane & 3) == 0) {
                    int row = mblk + wm * 64 + mt * 16 + (lane >> 2) + h * 8;
                    atomicAdd(&ssq[row], v);
                }
            }
        }
    }
}

// ---------------- small-world attention (rms folded in) ----------------------
__global__ __launch_bounds__(256)
void attn_kernel(const float* __restrict__ q, const float* __restrict__ k,
                 const float* __restrict__ v, const float* __restrict__ qn,
                 const float* __restrict__ kn, const float* __restrict__ eb,
                 const int* __restrict__ p_nf,
                 const float* __restrict__ ssq_q, const float* __restrict__ ssq_k,
                 uint32_t* __restrict__ ahi, unsigned char* __restrict__ a8)
{
    const int gwarp = (blockIdx.x * blockDim.x + threadIdx.x) >> 5;
    const int lane  = threadIdx.x & 31;
    const int token = gwarp >> 4;
    const int head  = gwarp & 15;

    int iv = *p_nf;
    int T;
    if (iv >= 1 && iv <= L_TOK && (L_TOK % iv) == 0) T = iv;
    else T = (int)__int_as_float(iv);
    const int S = L_TOK / T;

    const int t = token / S;
    const int s = token - t * S;
    const int qb = token * INNER + head * D_DIM;
    const int dim = head * D_DIM + 2 * lane;

    float rq = rsqrtf(ssq_q[token] * (1.0f / INNER) + 1e-6f);
    float2 qw = *(const float2*)&qn[dim];
    float2 kw = *(const float2*)&kn[dim];
    float2 qv = *(const float2*)&q[qb + 2 * lane];
    // fold qn_w*kn_w, scale, rq into q
    float pre = 0.125f * rq;
    qv.x *= qw.x * kw.x * pre;
    qv.y *= qw.y * kw.y * pre;

    float sc[NSHIFT], va[NSHIFT], vb[NSHIFT];
    #pragma unroll
    for (int n = 0; n < NSHIFT; n++) {
        int sft = c_shift[n];
        int tok2;
        if (n < 12) {
            int s2 = s + sft;
            while (s2 < 0)  s2 += S;
            while (s2 >= S) s2 -= S;
            tok2 = t * S + s2;
        } else {
            int t2 = t + sft;
            while (t2 < 0)  t2 += T;
            while (t2 >= T) t2 -= T;
            tok2 = t2 * S + s;
        }
        int nb = tok2 * INNER + head * D_DIM;
        float2 kv = *(const float2*)&k[nb + 2 * lane];
        float p = qv.x * kv.x + qv.y * kv.y;
        #pragma unroll
        for (int o = 16; o; o >>= 1) p += __shfl_xor_sync(0xffffffffu, p, o);
        float rk = rsqrtf(ssq_k[tok2] * (1.0f / INNER) + 1e-6f);
        sc[n] = p * rk + eb[head * NSHIFT + n];
        float2 vv = *(const float2*)&v[nb + 2 * lane];
        va[n] = vv.x; vb[n] = vv.y;
    }

    float m = sc[0];
    #pragma unroll
    for (int n = 1; n < NSHIFT; n++) m = fmaxf(m, sc[n]);
    float sum = 0.f;
    #pragma unroll
    for (int n = 0; n < NSHIFT; n++) { sc[n] = __expf(sc[n] - m); sum += sc[n]; }
    float inv = 1.0f / sum;

    float a0 = 0.f, a1 = 0.f;
    #pragma unroll
    for (int n = 0; n < NSHIFT; n++) {
        float w = sc[n] * inv;
        a0 += w * va[n];
        a1 += w * vb[n];
    }

    uint32_t hb; uint16_t h8, l8;
    pack3(a0, a1, hb, h8, l8);
    ahi[(uint32_t)token * 512 + head * 32 + lane] = hb;
    size_t base = (size_t)token * 2048 + head * 128 + 2 * lane;
    *(uint16_t*)&a8[base]      = h8;
    *(uint16_t*)&a8[base + 64] = l8;
}

// ---------------------------------------------------------------------------
extern "C" void kernel_launch(void* const* d_in, const int* in_sizes, int n_in,
                              void* d_out, int out_size)
{
    const float* x  = (const float*)d_in[0];
    const float* Wq = (const float*)d_in[1];
    const float* bq = (const float*)d_in[2];
    const float* Wk = (const float*)d_in[3];
    const float* bk = (const float*)d_in[4];
    const float* Wv = (const float*)d_in[5];
    const float* bv = (const float*)d_in[6];
    const float* qn = (const float*)d_in[7];
    const float* kn = (const float*)d_in[8];
    const float* eb = (const float*)d_in[9];
    const float* Wo = (const float*)d_in[10];
    const float* bo = (const float*)d_in[11];
    const int*   nf = (const int*)d_in[12];
    float* out = (float*)d_out;

    unsigned short *xhi,*ahi,*wqh,*woh;
    unsigned char  *x8,*a8,*wq8,*wo8;
    float *bqkv,*q,*k,*v,*ssq_q,*ssq_k;
    cudaGetSymbolAddress((void**)&xhi, g_xhi);
    cudaGetSymbolAddress((void**)&x8,  g_x8);
    cudaGetSymbolAddress((void**)&ahi, g_ahi);
    cudaGetSymbolAddress((void**)&a8,  g_a8);
    cudaGetSymbolAddress((void**)&wqh, g_wqkvhi);
    cudaGetSymbolAddress((void**)&wq8, g_wqkv8);
    cudaGetSymbolAddress((void**)&woh, g_wohi);
    cudaGetSymbolAddress((void**)&wo8, g_wo8);
    cudaGetSymbolAddress((void**)&bqkv, g_bqkv);
    cudaGetSymbolAddress((void**)&q, g_q);
    cudaGetSymbolAddress((void**)&k, g_k);
    cudaGetSymbolAddress((void**)&v, g_v);
    cudaGetSymbolAddress((void**)&ssq_q, g_ssq_q);
    cudaGetSymbolAddress((void**)&ssq_k, g_ssq_k);

    cudaFuncSetAttribute(gemm_mma, cudaFuncAttributeMaxDynamicSharedMemorySize, SMEM_TOTAL);

    init_misc<<<76, 256>>>(bq, bk, bv, bqkv, ssq_q, ssq_k);
    conv_x<<<4096, 256>>>(x, xhi, x8);
    conv_w<<<dim3(32, 32), 256>>>(Wq, wqh, wq8, 0);
    conv_w<<<dim3(32, 32), 256>>>(Wk, wqh, wq8, 1024);
    conv_w<<<dim3(32, 32), 256>>>(Wv, wqh, wq8, 2048);
    conv_w<<<dim3(32, 32), 256>>>(Wo, woh, wo8, 0);

    // fused QKV projection (N = 3072) + per-row sumsq for q,k
    gemm_mma<<<dim3(24, 64), 256, SMEM_TOTAL>>>(xhi, x8, wqh, wq8, bqkv,
                                                q, k, v, ssq_q, ssq_k, 0);

    attn_kernel<<<(L_TOK * H_NUM) / 8, 256>>>(q, k, v, qn, kn, eb, nf,
                                              ssq_q, ssq_k, (uint32_t*)ahi, a8);

    // output projection
    gemm_mma<<<dim3(8, 64), 256, SMEM_TOTAL>>>(ahi, a8, woh, wo8, bo,
                                               out, out, out, nullptr, nullptr, 1);
}

// round 6
// speedup vs baseline: 1.0567x; 1.0567x over previous
#include <cuda_runtime.h>
#include <cuda_bf16.h>
#include <cstdint>

#define L_TOK  8192
#define C_DIM  1024
#define INNER  1024
#define H_NUM  16
#define D_DIM  64
#define NSHIFT 16

#define BM 128
#define BN 128
#define NSTAGE 3
#define STAGE_BYTES 65536          // Ahi 16K | Alo 16K | Bhi 16K | Blo 16K
#define SMEM_TOTAL (NSTAGE * STAGE_BYTES)

// ---------------- scratch ----------------------------------------------------
__device__ __align__(256) unsigned short g_xhi [L_TOK * 1024];
__device__ __align__(256) unsigned short g_xlo [L_TOK * 1024];
__device__ __align__(256) unsigned short g_ahi [L_TOK * 1024];
__device__ __align__(256) unsigned short g_alo [L_TOK * 1024];
__device__ __align__(256) unsigned short g_wqkvhi[3072 * 1024];   // [n][k]
__device__ __align__(256) unsigned short g_wqkvlo[3072 * 1024];
__device__ __align__(256) unsigned short g_wohi[1024 * 1024];
__device__ __align__(256) unsigned short g_wolo[1024 * 1024];
__device__ float g_bqkv[3072];
__device__ float g_q[L_TOK * INNER];
__device__ float g_k[L_TOK * INNER];
__device__ float g_v[L_TOK * INNER];
__device__ float g_ssq_q[L_TOK];
__device__ float g_ssq_k[L_TOK];

__constant__ int c_shift[NSHIFT] = {1,-1,2,-2,4,-4,8,-8,16,-16,32,-32, 1,-1,2,-2};

// ---------------- helpers ---------------------------------------------------
__device__ __forceinline__ uint32_t smem_u32(const void* p){
    uint32_t a;
    asm("{ .reg .u64 t; cvta.to.shared.u64 t, %1; cvt.u32.u64 %0, t; }" : "=r"(a) : "l"(p));
    return a;
}
__device__ __forceinline__ void split_pair(float a, float b, uint32_t& hi, uint32_t& lo){
    __nv_bfloat16 h0 = __float2bfloat16(a), h1 = __float2bfloat16(b);
    float r0 = a - __bfloat162float(h0), r1 = b - __bfloat162float(h1);
    __nv_bfloat16 l0 = __float2bfloat16(r0), l1 = __float2bfloat16(r1);
    hi = (uint32_t)__bfloat16_as_ushort(h0) | ((uint32_t)__bfloat16_as_ushort(h1) << 16);
    lo = (uint32_t)__bfloat16_as_ushort(l0) | ((uint32_t)__bfloat16_as_ushort(l1) << 16);
}
__device__ __forceinline__ void cp16(uint32_t s, const void* g){
    asm volatile("cp.async.cg.shared.global [%0], [%1], 16;" :: "r"(s), "l"(g) : "memory");
}
__device__ __forceinline__ void ldsm_x4(uint32_t* r, uint32_t addr){
    asm volatile("ldmatrix.sync.aligned.m8n8.x4.shared.b16 {%0,%1,%2,%3}, [%4];"
        : "=r"(r[0]), "=r"(r[1]), "=r"(r[2]), "=r"(r[3]) : "r"(addr));
}
__device__ __forceinline__ void mma16816(float* d, const uint32_t* a, uint32_t b0, uint32_t b1){
    asm volatile("mma.sync.aligned.m16n8k16.row.col.f32.bf16.bf16.f32 "
        "{%0,%1,%2,%3}, {%4,%5,%6,%7}, {%8,%9}, {%0,%1,%2,%3};"
        : "+f"(d[0]), "+f"(d[1]), "+f"(d[2]), "+f"(d[3])
        : "r"(a[0]), "r"(a[1]), "r"(a[2]), "r"(a[3]), "r"(b0), "r"(b1));
}

// ---------------- converters -------------------------------------------------
__global__ __launch_bounds__(256)
void conv_x(const float* __restrict__ x, uint32_t* __restrict__ hi, uint32_t* __restrict__ lo)
{
    int gid = blockIdx.x * 256 + threadIdx.x;
    float2 f = ((const float2*)x)[gid];
    uint32_t h, l;
    split_pair(f.x, f.y, h, l);
    hi[gid] = h;
    lo[gid] = l;
}

__global__ __launch_bounds__(256)
void conv_w(const float* __restrict__ W, uint32_t* __restrict__ hi, uint32_t* __restrict__ lo,
            int n_off)
{
    __shared__ float tile[32][33];
    const int t = threadIdx.x;
    const int tx = t & 31, ty = t >> 5;
    const int k0 = blockIdx.x * 32, n0 = blockIdx.y * 32;
    #pragma unroll
    for (int r = 0; r < 4; r++) {
        int kl = ty + r * 8;
        tile[kl][tx] = W[(size_t)(k0 + kl) * 1024 + n0 + tx];
    }
    __syncthreads();
    #pragma unroll
    for (int w = 0; w < 2; w++) {
        int oid = t * 2 + w;
        int j = oid >> 4;
        int u = oid & 15;
        uint32_t h, l;
        split_pair(tile[2*u][j], tile[2*u+1][j], h, l);
        size_t idx = (size_t)(n_off + n0 + j) * 512 + (k0 >> 1) + u;
        hi[idx] = h;
        lo[idx] = l;
    }
}

__global__ void init_misc(const float* bq, const float* bk, const float* bv,
                          float* bqkv, float* ssq_q, float* ssq_k)
{
    int i = blockIdx.x * 256 + threadIdx.x;
    if (i < 1024)       bqkv[i] = bq[i];
    else if (i < 2048)  bqkv[i] = bk[i - 1024];
    else if (i < 3072)  bqkv[i] = bv[i - 2048];
    else {
        int j = i - 3072;
        if (j < L_TOK)          ssq_q[j] = 0.f;
        else if (j < 2*L_TOK)   ssq_k[j - L_TOK] = 0.f;
    }
}

// ---------------- bf16-split HMMA GEMM (3-term) ------------------------------
// mode 0: Ntot=3072 -> q/k/v outputs, + per-row sumsq for q,k.  mode 1: single.
__global__ __launch_bounds__(256, 1)
void gemm_mma(const unsigned short* __restrict__ Ahi, const unsigned short* __restrict__ Alo,
              const unsigned short* __restrict__ Bhi, const unsigned short* __restrict__ Blo,
              const float* __restrict__ bias,
              float* __restrict__ out0, float* __restrict__ out1, float* __restrict__ out2,
              float* __restrict__ ssq_q, float* __restrict__ ssq_k, int mode)
{
    extern __shared__ __align__(128) unsigned char smem[];
    const uint32_t sbase = smem_u32(smem);
    const int tid  = threadIdx.x;
    const int lane = tid & 31;
    const int wid  = tid >> 5;
    const int wm   = wid >> 2;
    const int wn   = wid & 3;
    const int mblk = blockIdx.y * BM;
    const int nblk = blockIdx.x * BN;

    auto load_stage = [&](int kc, int st){
        const uint32_t sb = sbase + st * STAGE_BYTES;
        #pragma unroll
        for (int mat = 0; mat < 4; mat++) {
            const unsigned short* gsrc;
            int rbase;
            if (mat == 0)      { gsrc = Ahi; rbase = mblk; }
            else if (mat == 1) { gsrc = Alo; rbase = mblk; }
            else if (mat == 2) { gsrc = Bhi; rbase = nblk; }
            else               { gsrc = Blo; rbase = nblk; }
            #pragma unroll
            for (int j = 0; j < 4; j++) {
                int id  = tid + j * 256;
                int row = id >> 3;
                int c   = id & 7;
                uint32_t soff = mat * 16384 + row * 128 + ((c ^ (row & 7)) << 4);
                const void* g = gsrc + (size_t)(rbase + row) * 1024 + kc * 64 + c * 8;
                cp16(sb + soff, g);
            }
        }
        asm volatile("cp.async.commit_group;" ::: "memory");
    };

    float acc[4][4][4];
    #pragma unroll
    for (int i = 0; i < 4; i++)
        #pragma unroll
        for (int j = 0; j < 4; j++)
            #pragma unroll
            for (int e = 0; e < 4; e++) acc[i][j][e] = 0.f;

    load_stage(0, 0);
    load_stage(1, 1);

    for (int kc = 0; kc < 16; kc++) {
        if (kc < 15) asm volatile("cp.async.wait_group 1;" ::: "memory");
        else         asm volatile("cp.async.wait_group 0;" ::: "memory");
        __syncthreads();

        const uint32_t sb = sbase + (kc % NSTAGE) * STAGE_BYTES;
        const uint32_t sAhi = sb, sAlo = sb + 16384, sBhi = sb + 32768, sBlo = sb + 49152;

        #pragma unroll
        for (int s = 0; s < 4; s++) {
            uint32_t ah[4][4], al[4][4];
            {
                int r = wm * 64 + (lane & 15);
                int c = 2 * s + (lane >> 4);
                #pragma unroll
                for (int mt = 0; mt < 4; mt++) {
                    int rr = r + mt * 16;
                    uint32_t off = rr * 128 + ((c ^ (rr & 7)) << 4);
                    ldsm_x4(ah[mt], sAhi + off);
                    ldsm_x4(al[mt], sAlo + off);
                }
            }
            uint32_t bh[4][2], bl[4][2];
            {
                int r = wn * 32 + (lane & 15);
                int c = 2 * s + (lane >> 4);
                #pragma unroll
                for (int p = 0; p < 2; p++) {
                    int rr = r + p * 16;
                    uint32_t off = rr * 128 + ((c ^ (rr & 7)) << 4);
                    uint32_t t4[4];
                    ldsm_x4(t4, sBhi + off);
                    bh[p*2+0][0] = t4[0]; bh[p*2+0][1] = t4[2];
                    bh[p*2+1][0] = t4[1]; bh[p*2+1][1] = t4[3];
                    ldsm_x4(t4, sBlo + off);
                    bl[p*2+0][0] = t4[0]; bl[p*2+0][1] = t4[2];
                    bl[p*2+1][0] = t4[1]; bl[p*2+1][1] = t4[3];
                }
            }
            #pragma unroll
            for (int mt = 0; mt < 4; mt++)
                #pragma unroll
                for (int nt = 0; nt < 4; nt++) {
                    mma16816(acc[mt][nt], ah[mt], bh[nt][0], bh[nt][1]);
                    mma16816(acc[mt][nt], ah[mt], bl[nt][0], bl[nt][1]);
                    mma16816(acc[mt][nt], al[mt], bh[nt][0], bh[nt][1]);
                }
        }
        __syncthreads();
        if (kc + 2 < 16) load_stage(kc + 2, (kc + 2) % NSTAGE);
    }

    // epilogue (+ per-row sumsq for q/k in mode 0)
    const int bi = nblk >> 10;
    float rsum[4][2];
    #pragma unroll
    for (int mt = 0; mt < 4; mt++) { rsum[mt][0] = 0.f; rsum[mt][1] = 0.f; }

    #pragma unroll
    for (int mt = 0; mt < 4; mt++) {
        #pragma unroll
        for (int nt = 0; nt < 4; nt++) {
            int m0  = mblk + wm * 64 + mt * 16 + (lane >> 2);
            int n_g = nblk + wn * 32 + nt * 8 + 2 * (lane & 3);
            float* dst; int nl;
            if (mode == 0) { dst = (bi == 0) ? out0 : (bi == 1) ? out1 : out2; nl = n_g & 1023; }
            else           { dst = out0; nl = n_g; }
            float b0 = bias[n_g], b1 = bias[n_g + 1];
            float vx0 = acc[mt][nt][0] + b0, vy0 = acc[mt][nt][1] + b1;
            float vx1 = acc[mt][nt][2] + b0, vy1 = acc[mt][nt][3] + b1;
            *(float2*)&dst[(size_t)m0 * 1024 + nl]       = make_float2(vx0, vy0);
            *(float2*)&dst[(size_t)(m0 + 8) * 1024 + nl] = make_float2(vx1, vy1);
            if (mode == 0 && bi < 2) {
                rsum[mt][0] += vx0 * vx0 + vy0 * vy0;
                rsum[mt][1] += vx1 * vx1 + vy1 * vy1;
            }
        }
    }
    if (mode == 0 && bi < 2) {
        float* ssq = (bi == 0) ? ssq_q : ssq_k;
        #pragma unroll
        for (int mt = 0; mt < 4; mt++) {
            #pragma unroll
            for (int h = 0; h < 2; h++) {
                float v = rsum[mt][h];
                v += __shfl_xor_sync(0xffffffffu, v, 1);
                v += __shfl_xor_sync(0xffffffffu, v, 2);
                if ((lane & 3) == 0) {
                    int row = mblk + wm * 64 + mt * 16 + (lane >> 2) + h * 8;
                    atomicAdd(&ssq[row], v);
                }
            }
        }
    }
}

// ---------------- small-world attention (rms folded in) ----------------------
__global__ __launch_bounds__(256)
void attn_kernel(const float* __restrict__ q, const float* __restrict__ k,
                 const float* __restrict__ v, const float* __restrict__ qn,
                 const float* __restrict__ kn, const float* __restrict__ eb,
                 const int* __restrict__ p_nf,
                 const float* __restrict__ ssq_q, const float* __restrict__ ssq_k,
                 uint32_t* __restrict__ ahi, uint32_t* __restrict__ alo)
{
    const int gwarp = (blockIdx.x * blockDim.x + threadIdx.x) >> 5;
    const int lane  = threadIdx.x & 31;
    const int token = gwarp >> 4;
    const int head  = gwarp & 15;

    int iv = *p_nf;
    int T;
    if (iv >= 1 && iv <= L_TOK && (L_TOK % iv) == 0) T = iv;
    else T = (int)__int_as_float(iv);
    const int S = L_TOK / T;

    const int t = token / S;
    const int s = token - t * S;
    const int qb = token * INNER + head * D_DIM;
    const int dim = head * D_DIM + 2 * lane;

    float rq = rsqrtf(ssq_q[token] * (1.0f / INNER) + 1e-6f);
    float2 qw = *(const float2*)&qn[dim];
    float2 kw = *(const float2*)&kn[dim];
    float2 qv = *(const float2*)&q[qb + 2 * lane];
    float pre = 0.125f * rq;
    qv.x *= qw.x * kw.x * pre;
    qv.y *= qw.y * kw.y * pre;

    float sc[NSHIFT], va[NSHIFT], vb[NSHIFT];
    #pragma unroll
    for (int n = 0; n < NSHIFT; n++) {
        int sft = c_shift[n];
        int tok2;
        if (n < 12) {
            int s2 = s + sft;
            while (s2 < 0)  s2 += S;
            while (s2 >= S) s2 -= S;
            tok2 = t * S + s2;
        } else {
            int t2 = t + sft;
            while (t2 < 0)  t2 += T;
            while (t2 >= T) t2 -= T;
            tok2 = t2 * S + s;
        }
        int nb = tok2 * INNER + head * D_DIM;
        float2 kv = *(const float2*)&k[nb + 2 * lane];
        float p = qv.x * kv.x + qv.y * kv.y;
        #pragma unroll
        for (int o = 16; o; o >>= 1) p += __shfl_xor_sync(0xffffffffu, p, o);
        float rk = rsqrtf(ssq_k[tok2] * (1.0f / INNER) + 1e-6f);
        sc[n] = p * rk + eb[head * NSHIFT + n];
        float2 vv = *(const float2*)&v[nb + 2 * lane];
        va[n] = vv.x; vb[n] = vv.y;
    }

    float m = sc[0];
    #pragma unroll
    for (int n = 1; n < NSHIFT; n++) m = fmaxf(m, sc[n]);
    float sum = 0.f;
    #pragma unroll
    for (int n = 0; n < NSHIFT; n++) { sc[n] = __expf(sc[n] - m); sum += sc[n]; }
    float inv = 1.0f / sum;

    float a0 = 0.f, a1 = 0.f;
    #pragma unroll
    for (int n = 0; n < NSHIFT; n++) {
        float w = sc[n] * inv;
        a0 += w * va[n];
        a1 += w * vb[n];
    }

    uint32_t h, l;
    split_pair(a0, a1, h, l);
    uint32_t idx = (uint32_t)token * 512 + head * 32 + lane;
    ahi[idx] = h;
    alo[idx] = l;
}

// ---------------------------------------------------------------------------
extern "C" void kernel_launch(void* const* d_in, const int* in_sizes, int n_in,
                              void* d_out, int out_size)
{
    const float* x  = (const float*)d_in[0];
    const float* Wq = (const float*)d_in[1];
    const float* bq = (const float*)d_in[2];
    const float* Wk = (const float*)d_in[3];
    const float* bk = (const float*)d_in[4];
    const float* Wv = (const float*)d_in[5];
    const float* bv = (const float*)d_in[6];
    const float* qn = (const float*)d_in[7];
    const float* kn = (const float*)d_in[8];
    const float* eb = (const float*)d_in[9];
    const float* Wo = (const float*)d_in[10];
    const float* bo = (const float*)d_in[11];
    const int*   nf = (const int*)d_in[12];
    float* out = (float*)d_out;

    unsigned short *xhi,*xlo,*ahi,*alo,*wqh,*wql,*woh,*wol;
    float *bqkv,*q,*k,*v,*ssq_q,*ssq_k;
    cudaGetSymbolAddress((void**)&xhi, g_xhi);
    cudaGetSymbolAddress((void**)&xlo, g_xlo);
    cudaGetSymbolAddress((void**)&ahi, g_ahi);
    cudaGetSymbolAddress((void**)&alo, g_alo);
    cudaGetSymbolAddress((void**)&wqh, g_wqkvhi);
    cudaGetSymbolAddress((void**)&wql, g_wqkvlo);
    cudaGetSymbolAddress((void**)&woh, g_wohi);
    cudaGetSymbolAddress((void**)&wol, g_wolo);
    cudaGetSymbolAddress((void**)&bqkv, g_bqkv);
    cudaGetSymbolAddress((void**)&q, g_q);
    cudaGetSymbolAddress((void**)&k, g_k);
    cudaGetSymbolAddress((void**)&v, g_v);
    cudaGetSymbolAddress((void**)&ssq_q, g_ssq_q);
    cudaGetSymbolAddress((void**)&ssq_k, g_ssq_k);

    cudaFuncSetAttribute(gemm_mma, cudaFuncAttributeMaxDynamicSharedMemorySize, SMEM_TOTAL);

    init_misc<<<76, 256>>>(bq, bk, bv, bqkv, ssq_q, ssq_k);
    conv_x<<<16384, 256>>>(x, (uint32_t*)xhi, (uint32_t*)xlo);
    conv_w<<<dim3(32, 32), 256>>>(Wq, (uint32_t*)wqh, (uint32_t*)wql, 0);
    conv_w<<<dim3(32, 32), 256>>>(Wk, (uint32_t*)wqh, (uint32_t*)wql, 1024);
    conv_w<<<dim3(32, 32), 256>>>(Wv, (uint32_t*)wqh, (uint32_t*)wql, 2048);
    conv_w<<<dim3(32, 32), 256>>>(Wo, (uint32_t*)woh, (uint32_t*)wol, 0);

    // fused QKV projection (N = 3072) + per-row sumsq for q,k
    gemm_mma<<<dim3(24, 64), 256, SMEM_TOTAL>>>(xhi, xlo, wqh, wql, bqkv,
                                                q, k, v, ssq_q, ssq_k, 0);

    attn_kernel<<<(L_TOK * H_NUM) / 8, 256>>>(q, k, v, qn, kn, eb, nf,
                                              ssq_q, ssq_k,
                                              (uint32_t*)ahi, (uint32_t*)alo);

    // output projection
    gemm_mma<<<dim3(8, 64), 256, SMEM_TOTAL>>>(ahi, alo, woh, wol, bo,
                                               out, out, out, nullptr, nullptr, 1);
}

// round 7
// speedup vs baseline: 1.3089x; 1.2386x over previous
#include <cuda_runtime.h>
#include <cuda_bf16.h>
#include <cuda_fp16.h>
#include <cstdint>

#define L_TOK  8192
#define C_DIM  1024
#define INNER  1024
#define H_NUM  16
#define D_DIM  64
#define NSHIFT 16

#define BM 128
#define BN 128
#define NSTAGE 3
// 3-term bf16 GEMM stages
#define STAGE_BYTES 65536          // Ahi 16K | Alo 16K | Bhi 16K | Blo 16K
#define SMEM_TOTAL (NSTAGE * STAGE_BYTES)
// 1-term fp16 GEMM stages
#define STAGE_QK 32768             // Af16 16K | Bf16 16K
#define SMEM_QK  (NSTAGE * STAGE_QK)

// ---------------- scratch ----------------------------------------------------
__device__ __align__(256) unsigned short g_xf16[L_TOK * 1024];     // fp16 1-term
__device__ __align__(256) unsigned short g_xhi [L_TOK * 1024];     // bf16 split
__device__ __align__(256) unsigned short g_xlo [L_TOK * 1024];
__device__ __align__(256) unsigned short g_ahi [L_TOK * 1024];
__device__ __align__(256) unsigned short g_alo [L_TOK * 1024];
__device__ __align__(256) unsigned short g_wqkf16[2048 * 1024];    // [n][k] fp16
__device__ __align__(256) unsigned short g_wvhi[1024 * 1024];      // [n][k]
__device__ __align__(256) unsigned short g_wvlo[1024 * 1024];
__device__ __align__(256) unsigned short g_wohi[1024 * 1024];
__device__ __align__(256) unsigned short g_wolo[1024 * 1024];
__device__ float g_bqk[2048];
__device__ float g_q[L_TOK * INNER];
__device__ float g_k[L_TOK * INNER];
__device__ float g_v[L_TOK * INNER];
__device__ float g_ssq_q[L_TOK];
__device__ float g_ssq_k[L_TOK];

__constant__ int c_shift[NSHIFT] = {1,-1,2,-2,4,-4,8,-8,16,-16,32,-32, 1,-1,2,-2};

// ---------------- helpers ---------------------------------------------------
__device__ __forceinline__ uint32_t smem_u32(const void* p){
    uint32_t a;
    asm("{ .reg .u64 t; cvta.to.shared.u64 t, %1; cvt.u32.u64 %0, t; }" : "=r"(a) : "l"(p));
    return a;
}
__device__ __forceinline__ void split_pair(float a, float b, uint32_t& hi, uint32_t& lo){
    __nv_bfloat16 h0 = __float2bfloat16(a), h1 = __float2bfloat16(b);
    float r0 = a - __bfloat162float(h0), r1 = b - __bfloat162float(h1);
    __nv_bfloat16 l0 = __float2bfloat16(r0), l1 = __float2bfloat16(r1);
    hi = (uint32_t)__bfloat16_as_ushort(h0) | ((uint32_t)__bfloat16_as_ushort(h1) << 16);
    lo = (uint32_t)__bfloat16_as_ushort(l0) | ((uint32_t)__bfloat16_as_ushort(l1) << 16);
}
__device__ __forceinline__ uint32_t pack_h2(float a, float b){
    __half2 h = __floats2half2_rn(a, b);
    return *(uint32_t*)&h;
}
__device__ __forceinline__ void cp16(uint32_t s, const void* g){
    asm volatile("cp.async.cg.shared.global [%0], [%1], 16;" :: "r"(s), "l"(g) : "memory");
}
__device__ __forceinline__ void ldsm_x4(uint32_t* r, uint32_t addr){
    asm volatile("ldmatrix.sync.aligned.m8n8.x4.shared.b16 {%0,%1,%2,%3}, [%4];"
        : "=r"(r[0]), "=r"(r[1]), "=r"(r[2]), "=r"(r[3]) : "r"(addr));
}
__device__ __forceinline__ void mma_bf16(float* d, const uint32_t* a, uint32_t b0, uint32_t b1){
    asm volatile("mma.sync.aligned.m16n8k16.row.col.f32.bf16.bf16.f32 "
        "{%0,%1,%2,%3}, {%4,%5,%6,%7}, {%8,%9}, {%0,%1,%2,%3};"
        : "+f"(d[0]), "+f"(d[1]), "+f"(d[2]), "+f"(d[3])
        : "r"(a[0]), "r"(a[1]), "r"(a[2]), "r"(a[3]), "r"(b0), "r"(b1));
}
__device__ __forceinline__ void mma_f16(float* d, const uint32_t* a, uint32_t b0, uint32_t b1){
    asm volatile("mma.sync.aligned.m16n8k16.row.col.f32.f16.f16.f32 "
        "{%0,%1,%2,%3}, {%4,%5,%6,%7}, {%8,%9}, {%0,%1,%2,%3};"
        : "+f"(d[0]), "+f"(d[1]), "+f"(d[2]), "+f"(d[3])
        : "r"(a[0]), "r"(a[1]), "r"(a[2]), "r"(a[3]), "r"(b0), "r"(b1));
}

// ---------------- converters -------------------------------------------------
// x fp32 -> fp16 (1-term) + bf16 hi/lo (split); 2 elems/thread
__global__ __launch_bounds__(256)
void conv_x(const float* __restrict__ x, uint32_t* __restrict__ f16,
            uint32_t* __restrict__ hi, uint32_t* __restrict__ lo)
{
    int gid = blockIdx.x * 256 + threadIdx.x;
    float2 f = ((const float2*)x)[gid];
    uint32_t h, l;
    split_pair(f.x, f.y, h, l);
    f16[gid] = pack_h2(f.x, f.y);
    hi[gid] = h;
    lo[gid] = l;
}

// W [k][n] fp32 -> [n][k] bf16 hi/lo
__global__ __launch_bounds__(256)
void conv_w(const float* __restrict__ W, uint32_t* __restrict__ hi, uint32_t* __restrict__ lo)
{
    __shared__ float tile[32][33];
    const int t = threadIdx.x;
    const int tx = t & 31, ty = t >> 5;
    const int k0 = blockIdx.x * 32, n0 = blockIdx.y * 32;
    #pragma unroll
    for (int r = 0; r < 4; r++) {
        int kl = ty + r * 8;
        tile[kl][tx] = W[(size_t)(k0 + kl) * 1024 + n0 + tx];
    }
    __syncthreads();
    #pragma unroll
    for (int w = 0; w < 2; w++) {
        int oid = t * 2 + w;
        int j = oid >> 4;
        int u = oid & 15;
        uint32_t h, l;
        split_pair(tile[2*u][j], tile[2*u+1][j], h, l);
        size_t idx = (size_t)(n0 + j) * 512 + (k0 >> 1) + u;
        hi[idx] = h;
        lo[idx] = l;
    }
}

// W [k][n] fp32 -> [n][k] fp16 (1-term), n offset for q/k concat
__global__ __launch_bounds__(256)
void conv_w_f16(const float* __restrict__ W, uint32_t* __restrict__ dst, int n_off)
{
    __shared__ float tile[32][33];
    const int t = threadIdx.x;
    const int tx = t & 31, ty = t >> 5;
    const int k0 = blockIdx.x * 32, n0 = blockIdx.y * 32;
    #pragma unroll
    for (int r = 0; r < 4; r++) {
        int kl = ty + r * 8;
        tile[kl][tx] = W[(size_t)(k0 + kl) * 1024 + n0 + tx];
    }
    __syncthreads();
    #pragma unroll
    for (int w = 0; w < 2; w++) {
        int oid = t * 2 + w;
        int j = oid >> 4;
        int u = oid & 15;
        size_t idx = (size_t)(n_off + n0 + j) * 512 + (k0 >> 1) + u;
        dst[idx] = pack_h2(tile[2*u][j], tile[2*u+1][j]);
    }
}

__global__ void init_misc(const float* bq, const float* bk,
                          float* bqk, float* ssq_q, float* ssq_k)
{
    int i = blockIdx.x * 256 + threadIdx.x;
    if (i < 1024)       bqk[i] = bq[i];
    else if (i < 2048)  bqk[i] = bk[i - 1024];
    else {
        int j = i - 2048;
        if (j < L_TOK)          ssq_q[j] = 0.f;
        else if (j < 2*L_TOK)   ssq_k[j - L_TOK] = 0.f;
    }
}

// ---------------- 1-term fp16 GEMM for Q,K (+ per-row sumsq) -----------------
// A = xf16 [8192][1024], B = wqkf16 [2048][1024] ([n][k]).  N 0..1023 -> q, rest -> k.
__global__ __launch_bounds__(256, 1)
void gemm_qk(const unsigned short* __restrict__ A, const unsigned short* __restrict__ B,
             const float* __restrict__ bias,
             float* __restrict__ outq, float* __restrict__ outk,
             float* __restrict__ ssq_q, float* __restrict__ ssq_k)
{
    extern __shared__ __align__(128) unsigned char smem[];
    const uint32_t sbase = smem_u32(smem);
    const int tid  = threadIdx.x;
    const int lane = tid & 31;
    const int wid  = tid >> 5;
    const int wm   = wid >> 2;
    const int wn   = wid & 3;
    const int mblk = blockIdx.y * BM;
    const int nblk = blockIdx.x * BN;

    auto load_stage = [&](int kc, int st){
        const uint32_t sb = sbase + st * STAGE_QK;
        #pragma unroll
        for (int mat = 0; mat < 2; mat++) {
            const unsigned short* gsrc = mat ? B : A;
            int rbase = mat ? nblk : mblk;
            #pragma unroll
            for (int j = 0; j < 4; j++) {
                int id  = tid + j * 256;
                int row = id >> 3;
                int c   = id & 7;
                uint32_t soff = mat * 16384 + row * 128 + ((c ^ (row & 7)) << 4);
                const void* g = gsrc + (size_t)(rbase + row) * 1024 + kc * 64 + c * 8;
                cp16(sb + soff, g);
            }
        }
        asm volatile("cp.async.commit_group;" ::: "memory");
    };

    float acc[4][4][4];
    #pragma unroll
    for (int i = 0; i < 4; i++)
        #pragma unroll
        for (int j = 0; j < 4; j++)
            #pragma unroll
            for (int e = 0; e < 4; e++) acc[i][j][e] = 0.f;

    load_stage(0, 0);
    load_stage(1, 1);

    for (int kc = 0; kc < 16; kc++) {
        if (kc < 15) asm volatile("cp.async.wait_group 1;" ::: "memory");
        else         asm volatile("cp.async.wait_group 0;" ::: "memory");
        __syncthreads();

        const uint32_t sb = sbase + (kc % NSTAGE) * STAGE_QK;
        const uint32_t sA = sb, sB = sb + 16384;

        #pragma unroll
        for (int s = 0; s < 4; s++) {
            uint32_t af[4][4];
            {
                int r = wm * 64 + (lane & 15);
                int c = 2 * s + (lane >> 4);
                #pragma unroll
                for (int mt = 0; mt < 4; mt++) {
                    int rr = r + mt * 16;
                    ldsm_x4(af[mt], sA + rr * 128 + ((c ^ (rr & 7)) << 4));
                }
            }
            uint32_t bf[4][2];
            {
                int r = wn * 32 + (lane & 15);
                int c = 2 * s + (lane >> 4);
                #pragma unroll
                for (int p = 0; p < 2; p++) {
                    int rr = r + p * 16;
                    uint32_t t4[4];
                    ldsm_x4(t4, sB + rr * 128 + ((c ^ (rr & 7)) << 4));
                    bf[p*2+0][0] = t4[0]; bf[p*2+0][1] = t4[2];
                    bf[p*2+1][0] = t4[1]; bf[p*2+1][1] = t4[3];
                }
            }
            #pragma unroll
            for (int mt = 0; mt < 4; mt++)
                #pragma unroll
                for (int nt = 0; nt < 4; nt++)
                    mma_f16(acc[mt][nt], af[mt], bf[nt][0], bf[nt][1]);
        }
        __syncthreads();
        if (kc + 2 < 16) load_stage(kc + 2, (kc + 2) % NSTAGE);
    }

    // epilogue: bias + store + per-row sumsq
    const int bi = nblk >> 10;                     // 0 = q, 1 = k
    float* dst = bi ? outk : outq;
    float* ssq = bi ? ssq_k : ssq_q;
    float rsum[4][2];
    #pragma unroll
    for (int mt = 0; mt < 4; mt++) { rsum[mt][0] = 0.f; rsum[mt][1] = 0.f; }

    #pragma unroll
    for (int mt = 0; mt < 4; mt++) {
        #pragma unroll
        for (int nt = 0; nt < 4; nt++) {
            int m0  = mblk + wm * 64 + mt * 16 + (lane >> 2);
            int n_g = nblk + wn * 32 + nt * 8 + 2 * (lane & 3);
            int nl  = n_g & 1023;
            float b0 = bias[n_g], b1 = bias[n_g + 1];
            float vx0 = acc[mt][nt][0] + b0, vy0 = acc[mt][nt][1] + b1;
            float vx1 = acc[mt][nt][2] + b0, vy1 = acc[mt][nt][3] + b1;
            *(float2*)&dst[(size_t)m0 * 1024 + nl]       = make_float2(vx0, vy0);
            *(float2*)&dst[(size_t)(m0 + 8) * 1024 + nl] = make_float2(vx1, vy1);
            rsum[mt][0] += vx0 * vx0 + vy0 * vy0;
            rsum[mt][1] += vx1 * vx1 + vy1 * vy1;
        }
    }
    #pragma unroll
    for (int mt = 0; mt < 4; mt++) {
        #pragma unroll
        for (int h = 0; h < 2; h++) {
            float v = rsum[mt][h];
            v += __shfl_xor_sync(0xffffffffu, v, 1);
            v += __shfl_xor_sync(0xffffffffu, v, 2);
            if ((lane & 3) == 0) {
                int row = mblk + wm * 64 + mt * 16 + (lane >> 2) + h * 8;
                atomicAdd(&ssq[row], v);
            }
        }
    }
}

// ---------------- 3-term bf16-split HMMA GEMM (V + out-proj) -----------------
__global__ __launch_bounds__(256, 1)
void gemm_mma(const unsigned short* __restrict__ Ahi, const unsigned short* __restrict__ Alo,
              const unsigned short* __restrict__ Bhi, const unsigned short* __restrict__ Blo,
              const float* __restrict__ bias, float* __restrict__ out)
{
    extern __shared__ __align__(128) unsigned char smem[];
    const uint32_t sbase = smem_u32(smem);
    const int tid  = threadIdx.x;
    const int lane = tid & 31;
    const int wid  = tid >> 5;
    const int wm   = wid >> 2;
    const int wn   = wid & 3;
    const int mblk = blockIdx.y * BM;
    const int nblk = blockIdx.x * BN;

    auto load_stage = [&](int kc, int st){
        const uint32_t sb = sbase + st * STAGE_BYTES;
        #pragma unroll
        for (int mat = 0; mat < 4; mat++) {
            const unsigned short* gsrc;
            int rbase;
            if (mat == 0)      { gsrc = Ahi; rbase = mblk; }
            else if (mat == 1) { gsrc = Alo; rbase = mblk; }
            else if (mat == 2) { gsrc = Bhi; rbase = nblk; }
            else               { gsrc = Blo; rbase = nblk; }
            #pragma unroll
            for (int j = 0; j < 4; j++) {
                int id  = tid + j * 256;
                int row = id >> 3;
                int c   = id & 7;
                uint32_t soff = mat * 16384 + row * 128 + ((c ^ (row & 7)) << 4);
                const void* g = gsrc + (size_t)(rbase + row) * 1024 + kc * 64 + c * 8;
                cp16(sb + soff, g);
            }
        }
        asm volatile("cp.async.commit_group;" ::: "memory");
    };

    float acc[4][4][4];
    #pragma unroll
    for (int i = 0; i < 4; i++)
        #pragma unroll
        for (int j = 0; j < 4; j++)
            #pragma unroll
            for (int e = 0; e < 4; e++) acc[i][j][e] = 0.f;

    load_stage(0, 0);
    load_stage(1, 1);

    for (int kc = 0; kc < 16; kc++) {
        if (kc < 15) asm volatile("cp.async.wait_group 1;" ::: "memory");
        else         asm volatile("cp.async.wait_group 0;" ::: "memory");
        __syncthreads();

        const uint32_t sb = sbase + (kc % NSTAGE) * STAGE_BYTES;
        const uint32_t sAhi = sb, sAlo = sb + 16384, sBhi = sb + 32768, sBlo = sb + 49152;

        #pragma unroll
        for (int s = 0; s < 4; s++) {
            uint32_t ah[4][4], al[4][4];
            {
                int r = wm * 64 + (lane & 15);
                int c = 2 * s + (lane >> 4);
                #pragma unroll
                for (int mt = 0; mt < 4; mt++) {
                    int rr = r + mt * 16;
                    uint32_t off = rr * 128 + ((c ^ (rr & 7)) << 4);
                    ldsm_x4(ah[mt], sAhi + off);
                    ldsm_x4(al[mt], sAlo + off);
                }
            }
            uint32_t bh[4][2], bl[4][2];
            {
                int r = wn * 32 + (lane & 15);
                int c = 2 * s + (lane >> 4);
                #pragma unroll
                for (int p = 0; p < 2; p++) {
                    int rr = r + p * 16;
                    uint32_t off = rr * 128 + ((c ^ (rr & 7)) << 4);
                    uint32_t t4[4];
                    ldsm_x4(t4, sBhi + off);
                    bh[p*2+0][0] = t4[0]; bh[p*2+0][1] = t4[2];
                    bh[p*2+1][0] = t4[1]; bh[p*2+1][1] = t4[3];
                    ldsm_x4(t4, sBlo + off);
                    bl[p*2+0][0] = t4[0]; bl[p*2+0][1] = t4[2];
                    bl[p*2+1][0] = t4[1]; bl[p*2+1][1] = t4[3];
                }
            }
            #pragma unroll
            for (int mt = 0; mt < 4; mt++)
                #pragma unroll
                for (int nt = 0; nt < 4; nt++) {
                    mma_bf16(acc[mt][nt], ah[mt], bh[nt][0], bh[nt][1]);
                    mma_bf16(acc[mt][nt], ah[mt], bl[nt][0], bl[nt][1]);
                    mma_bf16(acc[mt][nt], al[mt], bh[nt][0], bh[nt][1]);
                }
        }
        __syncthreads();
        if (kc + 2 < 16) load_stage(kc + 2, (kc + 2) % NSTAGE);
    }

    #pragma unroll
    for (int mt = 0; mt < 4; mt++) {
        #pragma unroll
        for (int nt = 0; nt < 4; nt++) {
            int m0  = mblk + wm * 64 + mt * 16 + (lane >> 2);
            int n_g = nblk + wn * 32 + nt * 8 + 2 * (lane & 3);
            float b0 = bias[n_g], b1 = bias[n_g + 1];
            float2 v0 = make_float2(acc[mt][nt][0] + b0, acc[mt][nt][1] + b1);
            float2 v1 = make_float2(acc[mt][nt][2] + b0, acc[mt][nt][3] + b1);
            *(float2*)&out[(size_t)m0 * 1024 + n_g]       = v0;
            *(float2*)&out[(size_t)(m0 + 8) * 1024 + n_g] = v1;
        }
    }
}

// ---------------- small-world attention (rms folded in) ----------------------
__global__ __launch_bounds__(256)
void attn_kernel(const float* __restrict__ q, const float* __restrict__ k,
                 const float* __restrict__ v, const float* __restrict__ qn,
                 const float* __restrict__ kn, const float* __restrict__ eb,
                 const int* __restrict__ p_nf,
                 const float* __restrict__ ssq_q, const float* __restrict__ ssq_k,
                 uint32_t* __restrict__ ahi, uint32_t* __restrict__ alo)
{
    const int gwarp = (blockIdx.x * blockDim.x + threadIdx.x) >> 5;
    const int lane  = threadIdx.x & 31;
    const int token = gwarp >> 4;
    const int head  = gwarp & 15;

    int iv = *p_nf;
    int T;
    if (iv >= 1 && iv <= L_TOK && (L_TOK % iv) == 0) T = iv;
    else T = (int)__int_as_float(iv);
    const int S = L_TOK / T;

    const int t = token / S;
    const int s = token - t * S;
    const int qb = token * INNER + head * D_DIM;
    const int dim = head * D_DIM + 2 * lane;

    float rq = rsqrtf(ssq_q[token] * (1.0f / INNER) + 1e-6f);
    float2 qw = *(const float2*)&qn[dim];
    float2 kw = *(const float2*)&kn[dim];
    float2 qv = *(const float2*)&q[qb + 2 * lane];
    float pre = 0.125f * rq;
    qv.x *= qw.x * kw.x * pre;
    qv.y *= qw.y * kw.y * pre;

    float sc[NSHIFT], va[NSHIFT], vb[NSHIFT];
    #pragma unroll
    for (int n = 0; n < NSHIFT; n++) {
        int sft = c_shift[n];
        int tok2;
        if (n < 12) {
            int s2 = s + sft;
            while (s2 < 0)  s2 += S;
            while (s2 >= S) s2 -= S;
            tok2 = t * S + s2;
        } else {
            int t2 = t + sft;
            while (t2 < 0)  t2 += T;
            while (t2 >= T) t2 -= T;
            tok2 = t2 * S + s;
        }
        int nb = tok2 * INNER + head * D_DIM;
        float2 kv = *(const float2*)&k[nb + 2 * lane];
        float p = qv.x * kv.x + qv.y * kv.y;
        #pragma unroll
        for (int o = 16; o; o >>= 1) p += __shfl_xor_sync(0xffffffffu, p, o);
        float rk = rsqrtf(ssq_k[tok2] * (1.0f / INNER) + 1e-6f);
        sc[n] = p * rk + eb[head * NSHIFT + n];
        float2 vv = *(const float2*)&v[nb + 2 * lane];
        va[n] = vv.x; vb[n] = vv.y;
    }

    float m = sc[0];
    #pragma unroll
    for (int n = 1; n < NSHIFT; n++) m = fmaxf(m, sc[n]);
    float sum = 0.f;
    #pragma unroll
    for (int n = 0; n < NSHIFT; n++) { sc[n] = __expf(sc[n] - m); sum += sc[n]; }
    float inv = 1.0f / sum;

    float a0 = 0.f, a1 = 0.f;
    #pragma unroll
    for (int n = 0; n < NSHIFT; n++) {
        float w = sc[n] * inv;
        a0 += w * va[n];
        a1 += w * vb[n];
    }

    uint32_t h, l;
    split_pair(a0, a1, h, l);
    uint32_t idx = (uint32_t)token * 512 + head * 32 + lane;
    ahi[idx] = h;
    alo[idx] = l;
}

// ---------------------------------------------------------------------------
extern "C" void kernel_launch(void* const* d_in, const int* in_sizes, int n_in,
                              void* d_out, int out_size)
{
    const float* x  = (const float*)d_in[0];
    const float* Wq = (const float*)d_in[1];
    const float* bq = (const float*)d_in[2];
    const float* Wk = (const float*)d_in[3];
    const float* bk = (const float*)d_in[4];
    const float* Wv = (const float*)d_in[5];
    const float* bv = (const float*)d_in[6];
    const float* qn = (const float*)d_in[7];
    const float* kn = (const float*)d_in[8];
    const float* eb = (const float*)d_in[9];
    const float* Wo = (const float*)d_in[10];
    const float* bo = (const float*)d_in[11];
    const int*   nf = (const int*)d_in[12];
    float* out = (float*)d_out;

    unsigned short *xf16,*xhi,*xlo,*ahi,*alo,*wqkf,*wvh,*wvl,*woh,*wol;
    float *bqk,*q,*k,*v,*ssq_q,*ssq_k;
    cudaGetSymbolAddress((void**)&xf16, g_xf16);
    cudaGetSymbolAddress((void**)&xhi, g_xhi);
    cudaGetSymbolAddress((void**)&xlo, g_xlo);
    cudaGetSymbolAddress((void**)&ahi, g_ahi);
    cudaGetSymbolAddress((void**)&alo, g_alo);
    cudaGetSymbolAddress((void**)&wqkf, g_wqkf16);
    cudaGetSymbolAddress((void**)&wvh, g_wvhi);
    cudaGetSymbolAddress((void**)&wvl, g_wvlo);
    cudaGetSymbolAddress((void**)&woh, g_wohi);
    cudaGetSymbolAddress((void**)&wol, g_wolo);
    cudaGetSymbolAddress((void**)&bqk, g_bqk);
    cudaGetSymbolAddress((void**)&q, g_q);
    cudaGetSymbolAddress((void**)&k, g_k);
    cudaGetSymbolAddress((void**)&v, g_v);
    cudaGetSymbolAddress((void**)&ssq_q, g_ssq_q);
    cudaGetSymbolAddress((void**)&ssq_k, g_ssq_k);

    cudaFuncSetAttribute(gemm_mma, cudaFuncAttributeMaxDynamicSharedMemorySize, SMEM_TOTAL);
    cudaFuncSetAttribute(gemm_qk,  cudaFuncAttributeMaxDynamicSharedMemorySize, SMEM_QK);

    init_misc<<<72, 256>>>(bq, bk, bqk, ssq_q, ssq_k);
    conv_x<<<16384, 256>>>(x, (uint32_t*)xf16, (uint32_t*)xhi, (uint32_t*)xlo);
    conv_w_f16<<<dim3(32, 32), 256>>>(Wq, (uint32_t*)wqkf, 0);
    conv_w_f16<<<dim3(32, 32), 256>>>(Wk, (uint32_t*)wqkf, 1024);
    conv_w<<<dim3(32, 32), 256>>>(Wv, (uint32_t*)wvh, (uint32_t*)wvl);
    conv_w<<<dim3(32, 32), 256>>>(Wo, (uint32_t*)woh, (uint32_t*)wol);

    // Q,K projections: 1-term fp16 (N = 2048) + per-row sumsq
    gemm_qk<<<dim3(16, 64), 256, SMEM_QK>>>(xf16, wqkf, bqk, q, k, ssq_q, ssq_k);

    // V projection: 3-term bf16
    gemm_mma<<<dim3(8, 64), 256, SMEM_TOTAL>>>(xhi, xlo, wvh, wvl, bv, v);

    attn_kernel<<<(L_TOK * H_NUM) / 8, 256>>>(q, k, v, qn, kn, eb, nf,
                                              ssq_q, ssq_k,
                                              (uint32_t*)ahi, (uint32_t*)alo);

    // output projection: 3-term bf16
    gemm_mma<<<dim3(8, 64), 256, SMEM_TOTAL>>>(ahi, alo, woh, wol, bo, out);
}

// round 8
// speedup vs baseline: 1.8621x; 1.4226x over previous
#include <cuda_runtime.h>
#include <cuda_bf16.h>
#include <cuda_fp16.h>
#include <cstdint>

#define L_TOK  8192
#define C_DIM  1024
#define INNER  1024
#define H_NUM  16
#define D_DIM  64
#define NSHIFT 16

#define BM 128
#define BN 128
#define NSTAGE 3
#define STAGE_F16 32768            // A 16K | B 16K
#define SMEM_F16  (NSTAGE * STAGE_F16)

// ---------------- scratch ----------------------------------------------------
__device__ __align__(256) unsigned short g_xf16[L_TOK * 1024];     // fp16 x
__device__ __align__(256) unsigned short g_af16[L_TOK * 1024];     // fp16 attn out
__device__ __align__(256) unsigned short g_wqkv16[3072 * 1024];    // [n][k] fp16
__device__ __align__(256) unsigned short g_wo16 [1024 * 1024];     // [n][k] fp16
__device__ float g_bqkv[3072];
__device__ float g_q[L_TOK * INNER];
__device__ float g_k[L_TOK * INNER];
__device__ float g_v[L_TOK * INNER];
__device__ float g_ssq_q[L_TOK];
__device__ float g_ssq_k[L_TOK];

__constant__ int c_shift[NSHIFT] = {1,-1,2,-2,4,-4,8,-8,16,-16,32,-32, 1,-1,2,-2};

// ---------------- helpers ---------------------------------------------------
__device__ __forceinline__ uint32_t smem_u32(const void* p){
    uint32_t a;
    asm("{ .reg .u64 t; cvta.to.shared.u64 t, %1; cvt.u32.u64 %0, t; }" : "=r"(a) : "l"(p));
    return a;
}
__device__ __forceinline__ uint32_t pack_h2(float a, float b){
    __half2 h = __floats2half2_rn(a, b);
    return *(uint32_t*)&h;
}
__device__ __forceinline__ void cp16(uint32_t s, const void* g){
    asm volatile("cp.async.cg.shared.global [%0], [%1], 16;" :: "r"(s), "l"(g) : "memory");
}
__device__ __forceinline__ void ldsm_x4(uint32_t* r, uint32_t addr){
    asm volatile("ldmatrix.sync.aligned.m8n8.x4.shared.b16 {%0,%1,%2,%3}, [%4];"
        : "=r"(r[0]), "=r"(r[1]), "=r"(r[2]), "=r"(r[3]) : "r"(addr));
}
__device__ __forceinline__ void mma_f16(float* d, const uint32_t* a, uint32_t b0, uint32_t b1){
    asm volatile("mma.sync.aligned.m16n8k16.row.col.f32.f16.f16.f32 "
        "{%0,%1,%2,%3}, {%4,%5,%6,%7}, {%8,%9}, {%0,%1,%2,%3};"
        : "+f"(d[0]), "+f"(d[1]), "+f"(d[2]), "+f"(d[3])
        : "r"(a[0]), "r"(a[1]), "r"(a[2]), "r"(a[3]), "r"(b0), "r"(b1));
}

// ---------------- converters -------------------------------------------------
// x fp32 -> fp16, 4 elems/thread
__global__ __launch_bounds__(256)
void conv_x(const float* __restrict__ x, uint32_t* __restrict__ f16)
{
    int gid = blockIdx.x * 256 + threadIdx.x;
    float4 f = ((const float4*)x)[gid];
    ((uint2*)f16)[gid] = make_uint2(pack_h2(f.x, f.y), pack_h2(f.z, f.w));
}

// W [k][n] fp32 -> [n][k] fp16, n offset for qkv concat
__global__ __launch_bounds__(256)
void conv_w_f16(const float* __restrict__ W, uint32_t* __restrict__ dst, int n_off)
{
    __shared__ float tile[32][33];
    const int t = threadIdx.x;
    const int tx = t & 31, ty = t >> 5;
    const int k0 = blockIdx.x * 32, n0 = blockIdx.y * 32;
    #pragma unroll
    for (int r = 0; r < 4; r++) {
        int kl = ty + r * 8;
        tile[kl][tx] = W[(size_t)(k0 + kl) * 1024 + n0 + tx];
    }
    __syncthreads();
    #pragma unroll
    for (int w = 0; w < 2; w++) {
        int oid = t * 2 + w;
        int j = oid >> 4;
        int u = oid & 15;
        size_t idx = (size_t)(n_off + n0 + j) * 512 + (k0 >> 1) + u;
        dst[idx] = pack_h2(tile[2*u][j], tile[2*u+1][j]);
    }
}

__global__ void init_misc(const float* bq, const float* bk, const float* bv,
                          float* bqkv, float* ssq_q, float* ssq_k)
{
    int i = blockIdx.x * 256 + threadIdx.x;
    if (i < 1024)       bqkv[i] = bq[i];
    else if (i < 2048)  bqkv[i] = bk[i - 1024];
    else if (i < 3072)  bqkv[i] = bv[i - 2048];
    else {
        int j = i - 3072;
        if (j < L_TOK)          ssq_q[j] = 0.f;
        else if (j < 2*L_TOK)   ssq_k[j - L_TOK] = 0.f;
    }
}

// ---------------- 1-term fp16 GEMM -------------------------------------------
// mode 0: Ntot=3072 -> q/k/v outputs (+ per-row sumsq for q,k).  mode 1: single.
__global__ __launch_bounds__(256, 1)
void gemm_f16(const unsigned short* __restrict__ A, const unsigned short* __restrict__ B,
              const float* __restrict__ bias,
              float* __restrict__ out0, float* __restrict__ out1, float* __restrict__ out2,
              float* __restrict__ ssq_q, float* __restrict__ ssq_k, int mode)
{
    extern __shared__ __align__(128) unsigned char smem[];
    const uint32_t sbase = smem_u32(smem);
    const int tid  = threadIdx.x;
    const int lane = tid & 31;
    const int wid  = tid >> 5;
    const int wm   = wid >> 2;
    const int wn   = wid & 3;
    const int mblk = blockIdx.y * BM;
    const int nblk = blockIdx.x * BN;

    auto load_stage = [&](int kc, int st){
        const uint32_t sb = sbase + st * STAGE_F16;
        #pragma unroll
        for (int mat = 0; mat < 2; mat++) {
            const unsigned short* gsrc = mat ? B : A;
            int rbase = mat ? nblk : mblk;
            #pragma unroll
            for (int j = 0; j < 4; j++) {
                int id  = tid + j * 256;
                int row = id >> 3;
                int c   = id & 7;
                uint32_t soff = mat * 16384 + row * 128 + ((c ^ (row & 7)) << 4);
                const void* g = gsrc + (size_t)(rbase + row) * 1024 + kc * 64 + c * 8;
                cp16(sb + soff, g);
            }
        }
        asm volatile("cp.async.commit_group;" ::: "memory");
    };

    float acc[4][4][4];
    #pragma unroll
    for (int i = 0; i < 4; i++)
        #pragma unroll
        for (int j = 0; j < 4; j++)
            #pragma unroll
            for (int e = 0; e < 4; e++) acc[i][j][e] = 0.f;

    load_stage(0, 0);
    load_stage(1, 1);

    for (int kc = 0; kc < 16; kc++) {
        if (kc < 15) asm volatile("cp.async.wait_group 1;" ::: "memory");
        else         asm volatile("cp.async.wait_group 0;" ::: "memory");
        __syncthreads();

        const uint32_t sb = sbase + (kc % NSTAGE) * STAGE_F16;
        const uint32_t sA = sb, sB = sb + 16384;

        #pragma unroll
        for (int s = 0; s < 4; s++) {
            uint32_t af[4][4];
            {
                int r = wm * 64 + (lane & 15);
                int c = 2 * s + (lane >> 4);
                #pragma unroll
                for (int mt = 0; mt < 4; mt++) {
                    int rr = r + mt * 16;
                    ldsm_x4(af[mt], sA + rr * 128 + ((c ^ (rr & 7)) << 4));
                }
            }
            uint32_t bf[4][2];
            {
                int r = wn * 32 + (lane & 15);
                int c = 2 * s + (lane >> 4);
                #pragma unroll
                for (int p = 0; p < 2; p++) {
                    int rr = r + p * 16;
                    uint32_t t4[4];
                    ldsm_x4(t4, sB + rr * 128 + ((c ^ (rr & 7)) << 4));
                    bf[p*2+0][0] = t4[0]; bf[p*2+0][1] = t4[2];
                    bf[p*2+1][0] = t4[1]; bf[p*2+1][1] = t4[3];
                }
            }
            #pragma unroll
            for (int mt = 0; mt < 4; mt++)
                #pragma unroll
                for (int nt = 0; nt < 4; nt++)
                    mma_f16(acc[mt][nt], af[mt], bf[nt][0], bf[nt][1]);
        }
        __syncthreads();
        if (kc + 2 < 16) load_stage(kc + 2, (kc + 2) % NSTAGE);
    }

    // epilogue
    const int bi = nblk >> 10;          // mode 0: 0=q 1=k 2=v
    float rsum[4][2];
    #pragma unroll
    for (int mt = 0; mt < 4; mt++) { rsum[mt][0] = 0.f; rsum[mt][1] = 0.f; }

    #pragma unroll
    for (int mt = 0; mt < 4; mt++) {
        #pragma unroll
        for (int nt = 0; nt < 4; nt++) {
            int m0  = mblk + wm * 64 + mt * 16 + (lane >> 2);
            int n_g = nblk + wn * 32 + nt * 8 + 2 * (lane & 3);
            float* dst; int nl;
            if (mode == 0) { dst = (bi == 0) ? out0 : (bi == 1) ? out1 : out2; nl = n_g & 1023; }
            else           { dst = out0; nl = n_g; }
            float b0 = bias[n_g], b1 = bias[n_g + 1];
            float vx0 = acc[mt][nt][0] + b0, vy0 = acc[mt][nt][1] + b1;
            float vx1 = acc[mt][nt][2] + b0, vy1 = acc[mt][nt][3] + b1;
            *(float2*)&dst[(size_t)m0 * 1024 + nl]       = make_float2(vx0, vy0);
            *(float2*)&dst[(size_t)(m0 + 8) * 1024 + nl] = make_float2(vx1, vy1);
            if (mode == 0 && bi < 2) {
                rsum[mt][0] += vx0 * vx0 + vy0 * vy0;
                rsum[mt][1] += vx1 * vx1 + vy1 * vy1;
            }
        }
    }
    if (mode == 0 && bi < 2) {
        float* ssq = bi ? ssq_k : ssq_q;
        #pragma unroll
        for (int mt = 0; mt < 4; mt++) {
            #pragma unroll
            for (int h = 0; h < 2; h++) {
                float v = rsum[mt][h];
                v += __shfl_xor_sync(0xffffffffu, v, 1);
                v += __shfl_xor_sync(0xffffffffu, v, 2);
                if ((lane & 3) == 0) {
                    int row = mblk + wm * 64 + mt * 16 + (lane >> 2) + h * 8;
                    atomicAdd(&ssq[row], v);
                }
            }
        }
    }
}

// ---------------- small-world attention (rms folded in, fp16 out) ------------
__global__ __launch_bounds__(256)
void attn_kernel(const float* __restrict__ q, const float* __restrict__ k,
                 const float* __restrict__ v, const float* __restrict__ qn,
                 const float* __restrict__ kn, const float* __restrict__ eb,
                 const int* __restrict__ p_nf,
                 const float* __restrict__ ssq_q, const float* __restrict__ ssq_k,
                 uint32_t* __restrict__ af16)
{
    const int gwarp = (blockIdx.x * blockDim.x + threadIdx.x) >> 5;
    const int lane  = threadIdx.x & 31;
    const int token = gwarp >> 4;
    const int head  = gwarp & 15;

    int iv = *p_nf;
    int T;
    if (iv >= 1 && iv <= L_TOK && (L_TOK % iv) == 0) T = iv;
    else T = (int)__int_as_float(iv);
    const int S = L_TOK / T;

    const int t = token / S;
    const int s = token - t * S;
    const int qb = token * INNER + head * D_DIM;
    const int dim = head * D_DIM + 2 * lane;

    float rq = rsqrtf(ssq_q[token] * (1.0f / INNER) + 1e-6f);
    float2 qw = *(const float2*)&qn[dim];
    float2 kw = *(const float2*)&kn[dim];
    float2 qv = *(const float2*)&q[qb + 2 * lane];
    float pre = 0.125f * rq;
    qv.x *= qw.x * kw.x * pre;
    qv.y *= qw.y * kw.y * pre;

    float sc[NSHIFT], va[NSHIFT], vb[NSHIFT];
    #pragma unroll
    for (int n = 0; n < NSHIFT; n++) {
        int sft = c_shift[n];
        int tok2;
        if (n < 12) {
            int s2 = s + sft;
            while (s2 < 0)  s2 += S;
            while (s2 >= S) s2 -= S;
            tok2 = t * S + s2;
        } else {
            int t2 = t + sft;
            while (t2 < 0)  t2 += T;
            while (t2 >= T) t2 -= T;
            tok2 = t2 * S + s;
        }
        int nb = tok2 * INNER + head * D_DIM;
        float2 kv = *(const float2*)&k[nb + 2 * lane];
        float p = qv.x * kv.x + qv.y * kv.y;
        #pragma unroll
        for (int o = 16; o; o >>= 1) p += __shfl_xor_sync(0xffffffffu, p, o);
        float rk = rsqrtf(ssq_k[tok2] * (1.0f / INNER) + 1e-6f);
        sc[n] = p * rk + eb[head * NSHIFT + n];
        float2 vv = *(const float2*)&v[nb + 2 * lane];
        va[n] = vv.x; vb[n] = vv.y;
    }

    float m = sc[0];
    #pragma unroll
    for (int n = 1; n < NSHIFT; n++) m = fmaxf(m, sc[n]);
    float sum = 0.f;
    #pragma unroll
    for (int n = 0; n < NSHIFT; n++) { sc[n] = __expf(sc[n] - m); sum += sc[n]; }
    float inv = 1.0f / sum;

    float a0 = 0.f, a1 = 0.f;
    #pragma unroll
    for (int n = 0; n < NSHIFT; n++) {
        float w = sc[n] * inv;
        a0 += w * va[n];
        a1 += w * vb[n];
    }

    af16[(uint32_t)token * 512 + head * 32 + lane] = pack_h2(a0, a1);
}

// ---------------------------------------------------------------------------
extern "C" void kernel_launch(void* const* d_in, const int* in_sizes, int n_in,
                              void* d_out, int out_size)
{
    const float* x  = (const float*)d_in[0];
    const float* Wq = (const float*)d_in[1];
    const float* bq = (const float*)d_in[2];
    const float* Wk = (const float*)d_in[3];
    const float* bk = (const float*)d_in[4];
    const float* Wv = (const float*)d_in[5];
    const float* bv = (const float*)d_in[6];
    const float* qn = (const float*)d_in[7];
    const float* kn = (const float*)d_in[8];
    const float* eb = (const float*)d_in[9];
    const float* Wo = (const float*)d_in[10];
    const float* bo = (const float*)d_in[11];
    const int*   nf = (const int*)d_in[12];
    float* out = (float*)d_out;

    unsigned short *xf16,*af16,*wqkv,*wo16;
    float *bqkv,*q,*k,*v,*ssq_q,*ssq_k;
    cudaGetSymbolAddress((void**)&xf16, g_xf16);
    cudaGetSymbolAddress((void**)&af16, g_af16);
    cudaGetSymbolAddress((void**)&wqkv, g_wqkv16);
    cudaGetSymbolAddress((void**)&wo16, g_wo16);
    cudaGetSymbolAddress((void**)&bqkv, g_bqkv);
    cudaGetSymbolAddress((void**)&q, g_q);
    cudaGetSymbolAddress((void**)&k, g_k);
    cudaGetSymbolAddress((void**)&v, g_v);
    cudaGetSymbolAddress((void**)&ssq_q, g_ssq_q);
    cudaGetSymbolAddress((void**)&ssq_k, g_ssq_k);

    cudaFuncSetAttribute(gemm_f16, cudaFuncAttributeMaxDynamicSharedMemorySize, SMEM_F16);

    init_misc<<<76, 256>>>(bq, bk, bv, bqkv, ssq_q, ssq_k);
    conv_x<<<8192, 256>>>(x, (uint32_t*)xf16);
    conv_w_f16<<<dim3(32, 32), 256>>>(Wq, (uint32_t*)wqkv, 0);
    conv_w_f16<<<dim3(32, 32), 256>>>(Wk, (uint32_t*)wqkv, 1024);
    conv_w_f16<<<dim3(32, 32), 256>>>(Wv, (uint32_t*)wqkv, 2048);
    conv_w_f16<<<dim3(32, 32), 256>>>(Wo, (uint32_t*)wo16, 0);

    // fused QKV projection (N = 3072) + per-row sumsq for q,k
    gemm_f16<<<dim3(24, 64), 256, SMEM_F16>>>(xf16, wqkv, bqkv,
                                              q, k, v, ssq_q, ssq_k, 0);

    attn_kernel<<<(L_TOK * H_NUM) / 8, 256>>>(q, k, v, qn, kn, eb, nf,
                                              ssq_q, ssq_k, (uint32_t*)af16);

    // output projection
    gemm_f16<<<dim3(8, 64), 256, SMEM_F16>>>(af16, wo16, bo,
                                             out, out, out, nullptr, nullptr, 1);
}

// round 9
// speedup vs baseline: 2.5622x; 1.3760x over previous
#include <cuda_runtime.h>
#include <cuda_bf16.h>
#include <cuda_fp16.h>
#include <cstdint>

#define L_TOK  8192
#define C_DIM  1024
#define INNER  1024
#define H_NUM  16
#define D_DIM  64
#define NSHIFT 16

#define BM 128
#define BN 128
#define NSTAGE 3
#define STAGE_F16 32768            // A 16K | B 16K
#define SMEM_F16  (NSTAGE * STAGE_F16)

// ---------------- scratch ----------------------------------------------------
__device__ __align__(256) unsigned short g_xf16[L_TOK * 1024];     // fp16 x
__device__ __align__(256) unsigned short g_af16[L_TOK * 1024];     // fp16 attn out
__device__ __align__(256) unsigned short g_wqkv16[3072 * 1024];    // [n][k] fp16
__device__ __align__(256) unsigned short g_wo16 [1024 * 1024];     // [n][k] fp16
__device__ __align__(256) unsigned short g_q16[L_TOK * 1024];      // fp16 q
__device__ __align__(256) unsigned short g_k16[L_TOK * 1024];      // fp16 k
__device__ __align__(256) unsigned short g_v16[L_TOK * 1024];      // fp16 v
__device__ float g_bqkv[3072];
__device__ float g_ssq_q[L_TOK];
__device__ float g_ssq_k[L_TOK];

__constant__ int c_shift[NSHIFT] = {1,-1,2,-2,4,-4,8,-8,16,-16,32,-32, 1,-1,2,-2};

// ---------------- helpers ---------------------------------------------------
__device__ __forceinline__ uint32_t smem_u32(const void* p){
    uint32_t a;
    asm("{ .reg .u64 t; cvta.to.shared.u64 t, %1; cvt.u32.u64 %0, t; }" : "=r"(a) : "l"(p));
    return a;
}
__device__ __forceinline__ uint32_t pack_h2(float a, float b){
    __half2 h = __floats2half2_rn(a, b);
    return *(uint32_t*)&h;
}
__device__ __forceinline__ float2 unpack_h2(uint32_t u){
    return __half22float2(*(__half2*)&u);
}
__device__ __forceinline__ void cp16(uint32_t s, const void* g){
    asm volatile("cp.async.cg.shared.global [%0], [%1], 16;" :: "r"(s), "l"(g) : "memory");
}
__device__ __forceinline__ void ldsm_x4(uint32_t* r, uint32_t addr){
    asm volatile("ldmatrix.sync.aligned.m8n8.x4.shared.b16 {%0,%1,%2,%3}, [%4];"
        : "=r"(r[0]), "=r"(r[1]), "=r"(r[2]), "=r"(r[3]) : "r"(addr));
}
__device__ __forceinline__ void mma_f16(float* d, const uint32_t* a, uint32_t b0, uint32_t b1){
    asm volatile("mma.sync.aligned.m16n8k16.row.col.f32.f16.f16.f32 "
        "{%0,%1,%2,%3}, {%4,%5,%6,%7}, {%8,%9}, {%0,%1,%2,%3};"
        : "+f"(d[0]), "+f"(d[1]), "+f"(d[2]), "+f"(d[3])
        : "r"(a[0]), "r"(a[1]), "r"(a[2]), "r"(a[3]), "r"(b0), "r"(b1));
}

// ---------------- converters -------------------------------------------------
__global__ __launch_bounds__(256)
void conv_x(const float* __restrict__ x, uint32_t* __restrict__ f16)
{
    int gid = blockIdx.x * 256 + threadIdx.x;
    float4 f = ((const float4*)x)[gid];
    ((uint2*)f16)[gid] = make_uint2(pack_h2(f.x, f.y), pack_h2(f.z, f.w));
}

// W [k][n] fp32 -> [n][k] fp16, n offset for qkv concat
__global__ __launch_bounds__(256)
void conv_w_f16(const float* __restrict__ W, uint32_t* __restrict__ dst, int n_off)
{
    __shared__ float tile[32][33];
    const int t = threadIdx.x;
    const int tx = t & 31, ty = t >> 5;
    const int k0 = blockIdx.x * 32, n0 = blockIdx.y * 32;
    #pragma unroll
    for (int r = 0; r < 4; r++) {
        int kl = ty + r * 8;
        tile[kl][tx] = W[(size_t)(k0 + kl) * 1024 + n0 + tx];
    }
    __syncthreads();
    #pragma unroll
    for (int w = 0; w < 2; w++) {
        int oid = t * 2 + w;
        int j = oid >> 4;
        int u = oid & 15;
        size_t idx = (size_t)(n_off + n0 + j) * 512 + (k0 >> 1) + u;
        dst[idx] = pack_h2(tile[2*u][j], tile[2*u+1][j]);
    }
}

__global__ void init_misc(const float* bq, const float* bk, const float* bv,
                          float* bqkv, float* ssq_q, float* ssq_k)
{
    int i = blockIdx.x * 256 + threadIdx.x;
    if (i < 1024)       bqkv[i] = bq[i];
    else if (i < 2048)  bqkv[i] = bk[i - 1024];
    else if (i < 3072)  bqkv[i] = bv[i - 2048];
    else {
        int j = i - 3072;
        if (j < L_TOK)          ssq_q[j] = 0.f;
        else if (j < 2*L_TOK)   ssq_k[j - L_TOK] = 0.f;
    }
}

// ---------------- 1-term fp16 GEMM -------------------------------------------
// mode 0: Ntot=3072 -> q/k/v (fp16 outputs) + per-row sumsq for q,k.
// mode 1: single fp32 output.
__global__ __launch_bounds__(256, 1)
void gemm_f16(const unsigned short* __restrict__ A, const unsigned short* __restrict__ B,
              const float* __restrict__ bias,
              void* __restrict__ out0, void* __restrict__ out1, void* __restrict__ out2,
              float* __restrict__ ssq_q, float* __restrict__ ssq_k, int mode)
{
    extern __shared__ __align__(128) unsigned char smem[];
    const uint32_t sbase = smem_u32(smem);
    const int tid  = threadIdx.x;
    const int lane = tid & 31;
    const int wid  = tid >> 5;
    const int wm   = wid >> 2;
    const int wn   = wid & 3;
    const int mblk = blockIdx.y * BM;
    const int nblk = blockIdx.x * BN;

    auto load_stage = [&](int kc, int st){
        const uint32_t sb = sbase + st * STAGE_F16;
        #pragma unroll
        for (int mat = 0; mat < 2; mat++) {
            const unsigned short* gsrc = mat ? B : A;
            int rbase = mat ? nblk : mblk;
            #pragma unroll
            for (int j = 0; j < 4; j++) {
                int id  = tid + j * 256;
                int row = id >> 3;
                int c   = id & 7;
                uint32_t soff = mat * 16384 + row * 128 + ((c ^ (row & 7)) << 4);
                const void* g = gsrc + (size_t)(rbase + row) * 1024 + kc * 64 + c * 8;
                cp16(sb + soff, g);
            }
        }
        asm volatile("cp.async.commit_group;" ::: "memory");
    };

    float acc[4][4][4];
    #pragma unroll
    for (int i = 0; i < 4; i++)
        #pragma unroll
        for (int j = 0; j < 4; j++)
            #pragma unroll
            for (int e = 0; e < 4; e++) acc[i][j][e] = 0.f;

    load_stage(0, 0);
    load_stage(1, 1);

    for (int kc = 0; kc < 16; kc++) {
        if (kc < 15) asm volatile("cp.async.wait_group 1;" ::: "memory");
        else         asm volatile("cp.async.wait_group 0;" ::: "memory");
        __syncthreads();

        const uint32_t sb = sbase + (kc % NSTAGE) * STAGE_F16;
        const uint32_t sA = sb, sB = sb + 16384;

        #pragma unroll
        for (int s = 0; s < 4; s++) {
            uint32_t af[4][4];
            {
                int r = wm * 64 + (lane & 15);
                int c = 2 * s + (lane >> 4);
                #pragma unroll
                for (int mt = 0; mt < 4; mt++) {
                    int rr = r + mt * 16;
                    ldsm_x4(af[mt], sA + rr * 128 + ((c ^ (rr & 7)) << 4));
                }
            }
            uint32_t bf[4][2];
            {
                int r = wn * 32 + (lane & 15);
                int c = 2 * s + (lane >> 4);
                #pragma unroll
                for (int p = 0; p < 2; p++) {
                    int rr = r + p * 16;
                    uint32_t t4[4];
                    ldsm_x4(t4, sB + rr * 128 + ((c ^ (rr & 7)) << 4));
                    bf[p*2+0][0] = t4[0]; bf[p*2+0][1] = t4[2];
                    bf[p*2+1][0] = t4[1]; bf[p*2+1][1] = t4[3];
                }
            }
            #pragma unroll
            for (int mt = 0; mt < 4; mt++)
                #pragma unroll
                for (int nt = 0; nt < 4; nt++)
                    mma_f16(acc[mt][nt], af[mt], bf[nt][0], bf[nt][1]);
        }
        __syncthreads();
        if (kc + 2 < 16) load_stage(kc + 2, (kc + 2) % NSTAGE);
    }

    // epilogue
    const int bi = nblk >> 10;          // mode 0: 0=q 1=k 2=v
    float rsum[4][2];
    #pragma unroll
    for (int mt = 0; mt < 4; mt++) { rsum[mt][0] = 0.f; rsum[mt][1] = 0.f; }

    #pragma unroll
    for (int mt = 0; mt < 4; mt++) {
        #pragma unroll
        for (int nt = 0; nt < 4; nt++) {
            int m0  = mblk + wm * 64 + mt * 16 + (lane >> 2);
            int n_g = nblk + wn * 32 + nt * 8 + 2 * (lane & 3);
            float b0 = bias[n_g], b1 = bias[n_g + 1];
            float vx0 = acc[mt][nt][0] + b0, vy0 = acc[mt][nt][1] + b1;
            float vx1 = acc[mt][nt][2] + b0, vy1 = acc[mt][nt][3] + b1;
            if (mode == 0) {
                uint32_t* dst = (uint32_t*)((bi == 0) ? out0 : (bi == 1) ? out1 : out2);
                int nl = n_g & 1023;
                dst[(size_t)m0 * 512 + (nl >> 1)]       = pack_h2(vx0, vy0);
                dst[(size_t)(m0 + 8) * 512 + (nl >> 1)] = pack_h2(vx1, vy1);
                if (bi < 2) {
                    rsum[mt][0] += vx0 * vx0 + vy0 * vy0;
                    rsum[mt][1] += vx1 * vx1 + vy1 * vy1;
                }
            } else {
                float* dst = (float*)out0;
                *(float2*)&dst[(size_t)m0 * 1024 + n_g]       = make_float2(vx0, vy0);
                *(float2*)&dst[(size_t)(m0 + 8) * 1024 + n_g] = make_float2(vx1, vy1);
            }
        }
    }
    if (mode == 0 && bi < 2) {
        float* ssq = bi ? ssq_k : ssq_q;
        #pragma unroll
        for (int mt = 0; mt < 4; mt++) {
            #pragma unroll
            for (int h = 0; h < 2; h++) {
                float v = rsum[mt][h];
                v += __shfl_xor_sync(0xffffffffu, v, 1);
                v += __shfl_xor_sync(0xffffffffu, v, 2);
                if ((lane & 3) == 0) {
                    int row = mblk + wm * 64 + mt * 16 + (lane >> 2) + h * 8;
                    atomicAdd(&ssq[row], v);
                }
            }
        }
    }
}

// ---------------- small-world attention ---------------------------------------
// One warp per (token, head-pair). Lane group (0-15 / 16-31) = one head,
// lane owns 4 dims (uint2 = 4 halves). 4-shfl 16-lane reduction.
__global__ __launch_bounds__(256)
void attn_kernel(const unsigned short* __restrict__ q16,
                 const unsigned short* __restrict__ k16,
                 const unsigned short* __restrict__ v16,
                 const float* __restrict__ qn, const float* __restrict__ kn,
                 const float* __restrict__ eb, const int* __restrict__ p_nf,
                 const float* __restrict__ ssq_q, const float* __restrict__ ssq_k,
                 uint32_t* __restrict__ af16)
{
    const int gwarp = (blockIdx.x * blockDim.x + threadIdx.x) >> 5;
    const int lane  = threadIdx.x & 31;
    const int token = gwarp >> 3;
    const int hp    = gwarp & 7;
    const int head  = hp * 2 + (lane >> 4);
    const int sub   = lane & 15;
    const int dim0  = head * D_DIM + sub * 4;

    int iv = *p_nf;
    int T;
    if (iv >= 1 && iv <= L_TOK && (L_TOK % iv) == 0) T = iv;
    else T = (int)__int_as_float(iv);
    const int S = L_TOK / T;

    const int t = token / S;
    const int s = token - t * S;

    float rq = rsqrtf(ssq_q[token] * (1.0f / INNER) + 1e-6f);
    float4 qw = *(const float4*)&qn[dim0];
    float4 kw = *(const float4*)&kn[dim0];
    uint2 qp = *(const uint2*)&q16[(size_t)token * 1024 + dim0];
    float2 qa = unpack_h2(qp.x), qb = unpack_h2(qp.y);
    float pre = 0.125f * rq;
    qa.x *= qw.x * kw.x * pre;  qa.y *= qw.y * kw.y * pre;
    qb.x *= qw.z * kw.z * pre;  qb.y *= qw.w * kw.w * pre;

    float sc[NSHIFT];
    uint2 vp[NSHIFT];
    #pragma unroll
    for (int n = 0; n < NSHIFT; n++) {
        int sft = c_shift[n];
        int tok2;
        if (n < 12) {
            int s2 = s + sft;
            while (s2 < 0)  s2 += S;
            while (s2 >= S) s2 -= S;
            tok2 = t * S + s2;
        } else {
            int t2 = t + sft;
            while (t2 < 0)  t2 += T;
            while (t2 >= T) t2 -= T;
            tok2 = t2 * S + s;
        }
        size_t nb = (size_t)tok2 * 1024 + dim0;
        uint2 kp = *(const uint2*)&k16[nb];
        float2 k0 = unpack_h2(kp.x), k1 = unpack_h2(kp.y);
        float p = qa.x * k0.x + qa.y * k0.y + qb.x * k1.x + qb.y * k1.y;
        p += __shfl_xor_sync(0xffffffffu, p, 8);
        p += __shfl_xor_sync(0xffffffffu, p, 4);
        p += __shfl_xor_sync(0xffffffffu, p, 2);
        p += __shfl_xor_sync(0xffffffffu, p, 1);
        float rk = rsqrtf(ssq_k[tok2] * (1.0f / INNER) + 1e-6f);
        sc[n] = p * rk + eb[head * NSHIFT + n];
        vp[n] = *(const uint2*)&v16[nb];
    }

    float m = sc[0];
    #pragma unroll
    for (int n = 1; n < NSHIFT; n++) m = fmaxf(m, sc[n]);
    float sum = 0.f;
    #pragma unroll
    for (int n = 0; n < NSHIFT; n++) { sc[n] = __expf(sc[n] - m); sum += sc[n]; }
    float inv = 1.0f / sum;

    float a0 = 0.f, a1 = 0.f, a2 = 0.f, a3 = 0.f;
    #pragma unroll
    for (int n = 0; n < NSHIFT; n++) {
        float w = sc[n] * inv;
        float2 v0 = unpack_h2(vp[n].x), v1 = unpack_h2(vp[n].y);
        a0 += w * v0.x; a1 += w * v0.y;
        a2 += w * v1.x; a3 += w * v1.y;
    }

    uint2 o = make_uint2(pack_h2(a0, a1), pack_h2(a2, a3));
    *(uint2*)&af16[(size_t)token * 512 + head * 32 + sub * 2] = o;
}

// ---------------------------------------------------------------------------
extern "C" void kernel_launch(void* const* d_in, const int* in_sizes, int n_in,
                              void* d_out, int out_size)
{
    const float* x  = (const float*)d_in[0];
    const float* Wq = (const float*)d_in[1];
    const float* bq = (const float*)d_in[2];
    const float* Wk = (const float*)d_in[3];
    const float* bk = (const float*)d_in[4];
    const float* Wv = (const float*)d_in[5];
    const float* bv = (const float*)d_in[6];
    const float* qn = (const float*)d_in[7];
    const float* kn = (const float*)d_in[8];
    const float* eb = (const float*)d_in[9];
    const float* Wo = (const float*)d_in[10];
    const float* bo = (const float*)d_in[11];
    const int*   nf = (const int*)d_in[12];
    float* out = (float*)d_out;

    unsigned short *xf16,*af16,*wqkv,*wo16,*q16,*k16,*v16;
    float *bqkv,*ssq_q,*ssq_k;
    cudaGetSymbolAddress((void**)&xf16, g_xf16);
    cudaGetSymbolAddress((void**)&af16, g_af16);
    cudaGetSymbolAddress((void**)&wqkv, g_wqkv16);
    cudaGetSymbolAddress((void**)&wo16, g_wo16);
    cudaGetSymbolAddress((void**)&q16, g_q16);
    cudaGetSymbolAddress((void**)&k16, g_k16);
    cudaGetSymbolAddress((void**)&v16, g_v16);
    cudaGetSymbolAddress((void**)&bqkv, g_bqkv);
    cudaGetSymbolAddress((void**)&ssq_q, g_ssq_q);
    cudaGetSymbolAddress((void**)&ssq_k, g_ssq_k);

    cudaFuncSetAttribute(gemm_f16, cudaFuncAttributeMaxDynamicSharedMemorySize, SMEM_F16);

    init_misc<<<76, 256>>>(bq, bk, bv, bqkv, ssq_q, ssq_k);
    conv_x<<<8192, 256>>>(x, (uint32_t*)xf16);
    conv_w_f16<<<dim3(32, 32), 256>>>(Wq, (uint32_t*)wqkv, 0);
    conv_w_f16<<<dim3(32, 32), 256>>>(Wk, (uint32_t*)wqkv, 1024);
    conv_w_f16<<<dim3(32, 32), 256>>>(Wv, (uint32_t*)wqkv, 2048);
    conv_w_f16<<<dim3(32, 32), 256>>>(Wo, (uint32_t*)wo16, 0);

    // fused QKV projection (N = 3072), fp16 outputs + per-row sumsq for q,k
    gemm_f16<<<dim3(24, 64), 256, SMEM_F16>>>(xf16, wqkv, bqkv,
                                              q16, k16, v16, ssq_q, ssq_k, 0);

    // attention: 8192 tokens x 8 head-pairs = 65536 warps
    attn_kernel<<<(L_TOK * 8) / 8, 256>>>(q16, k16, v16, qn, kn, eb, nf,
                                          ssq_q, ssq_k, (uint32_t*)af16);

    // output projection (fp32 out)
    gemm_f16<<<dim3(8, 64), 256, SMEM_F16>>>(af16, wo16, bo,
                                             out, out, out, nullptr, nullptr, 1);
}

// round 10
// speedup vs baseline: 2.5656x; 1.0013x over previous
#include <cuda_runtime.h>
#include <cuda_bf16.h>
#include <cuda_fp16.h>
#include <cstdint>

#define L_TOK  8192
#define C_DIM  1024
#define INNER  1024
#define H_NUM  16
#define D_DIM  64
#define NSHIFT 16

#define BM 128
#define BN 128
#define NSTAGE 3
#define STAGE_F16 32768            // A 16K | B 16K
#define SMEM_F16  (NSTAGE * STAGE_F16)

// ---------------- scratch ----------------------------------------------------
__device__ __align__(256) unsigned short g_xf16[L_TOK * 1024];     // fp16 x
__device__ __align__(256) unsigned short g_af16[L_TOK * 1024];     // fp16 attn out
__device__ __align__(256) unsigned short g_wqkv16[3072 * 1024];    // [n][k] fp16
__device__ __align__(256) unsigned short g_wo16 [1024 * 1024];     // [n][k] fp16
__device__ __align__(256) unsigned short g_q16[L_TOK * 1024];      // fp16 q
__device__ __align__(256) unsigned short g_k16[L_TOK * 1024];      // fp16 k
__device__ __align__(256) unsigned short g_v16[L_TOK * 1024];      // fp16 v
__device__ float g_bqkv[3072];
__device__ float g_ssq_q[L_TOK];
__device__ float g_ssq_k[L_TOK];

__constant__ int c_shift[NSHIFT] = {1,-1,2,-2,4,-4,8,-8,16,-16,32,-32, 1,-1,2,-2};

// ---------------- helpers ---------------------------------------------------
__device__ __forceinline__ uint32_t smem_u32(const void* p){
    uint32_t a;
    asm("{ .reg .u64 t; cvta.to.shared.u64 t, %1; cvt.u32.u64 %0, t; }" : "=r"(a) : "l"(p));
    return a;
}
__device__ __forceinline__ uint32_t pack_h2(float a, float b){
    __half2 h = __floats2half2_rn(a, b);
    return *(uint32_t*)&h;
}
__device__ __forceinline__ float2 unpack_h2(uint32_t u){
    return __half22float2(*(__half2*)&u);
}
__device__ __forceinline__ void cp16(uint32_t s, const void* g){
    asm volatile("cp.async.cg.shared.global [%0], [%1], 16;" :: "r"(s), "l"(g) : "memory");
}
__device__ __forceinline__ void ldsm_x4(uint32_t* r, uint32_t addr){
    asm volatile("ldmatrix.sync.aligned.m8n8.x4.shared.b16 {%0,%1,%2,%3}, [%4];"
        : "=r"(r[0]), "=r"(r[1]), "=r"(r[2]), "=r"(r[3]) : "r"(addr));
}
__device__ __forceinline__ void mma_f16(float* d, const uint32_t* a, uint32_t b0, uint32_t b1){
    asm volatile("mma.sync.aligned.m16n8k16.row.col.f32.f16.f16.f32 "
        "{%0,%1,%2,%3}, {%4,%5,%6,%7}, {%8,%9}, {%0,%1,%2,%3};"
        : "+f"(d[0]), "+f"(d[1]), "+f"(d[2]), "+f"(d[3])
        : "r"(a[0]), "r"(a[1]), "r"(a[2]), "r"(a[3]), "r"(b0), "r"(b1));
}

// ---------------- converters -------------------------------------------------
__global__ __launch_bounds__(256)
void conv_x(const float* __restrict__ x, uint32_t* __restrict__ f16)
{
    int gid = blockIdx.x * 256 + threadIdx.x;
    float4 f = ((const float4*)x)[gid];
    ((uint2*)f16)[gid] = make_uint2(pack_h2(f.x, f.y), pack_h2(f.z, f.w));
}

// All 4 weights in one launch. blockIdx.z: 0=Wq 1=Wk 2=Wv 3=Wo.
// W [k][n] fp32 -> [n][k] fp16 at concat offset.
__global__ __launch_bounds__(256)
void conv_w_all(const float* __restrict__ Wq, const float* __restrict__ Wk,
                const float* __restrict__ Wv, const float* __restrict__ Wo,
                uint32_t* __restrict__ wqkv, uint32_t* __restrict__ wo)
{
    __shared__ float tile[32][33];
    const int t = threadIdx.x;
    const int tx = t & 31, ty = t >> 5;
    const int k0 = blockIdx.x * 32, n0 = blockIdx.y * 32;
    const int z = blockIdx.z;
    const float* W = (z == 0) ? Wq : (z == 1) ? Wk : (z == 2) ? Wv : Wo;
    uint32_t* dst  = (z == 3) ? wo : wqkv;
    const int n_off = (z == 3) ? 0 : z * 1024;
    #pragma unroll
    for (int r = 0; r < 4; r++) {
        int kl = ty + r * 8;
        tile[kl][tx] = W[(size_t)(k0 + kl) * 1024 + n0 + tx];
    }
    __syncthreads();
    #pragma unroll
    for (int w = 0; w < 2; w++) {
        int oid = t * 2 + w;
        int j = oid >> 4;
        int u = oid & 15;
        size_t idx = (size_t)(n_off + n0 + j) * 512 + (k0 >> 1) + u;
        dst[idx] = pack_h2(tile[2*u][j], tile[2*u+1][j]);
    }
}

__global__ void init_misc(const float* bq, const float* bk, const float* bv,
                          float* bqkv, float* ssq_q, float* ssq_k)
{
    int i = blockIdx.x * 256 + threadIdx.x;
    if (i < 1024)       bqkv[i] = bq[i];
    else if (i < 2048)  bqkv[i] = bk[i - 1024];
    else if (i < 3072)  bqkv[i] = bv[i - 2048];
    else {
        int j = i - 3072;
        if (j < L_TOK)          ssq_q[j] = 0.f;
        else if (j < 2*L_TOK)   ssq_k[j - L_TOK] = 0.f;
    }
}

// ---------------- 1-term fp16 GEMM (2 CTAs/SM) -------------------------------
// mode 0: Ntot=3072 -> q/k/v (fp16 outputs) + per-row sumsq for q,k.
// mode 1: single fp32 output.
__global__ __launch_bounds__(256, 2)
void gemm_f16(const unsigned short* __restrict__ A, const unsigned short* __restrict__ B,
              const float* __restrict__ bias,
              void* __restrict__ out0, void* __restrict__ out1, void* __restrict__ out2,
              float* __restrict__ ssq_q, float* __restrict__ ssq_k, int mode)
{
    extern __shared__ __align__(128) unsigned char smem[];
    const uint32_t sbase = smem_u32(smem);
    const int tid  = threadIdx.x;
    const int lane = tid & 31;
    const int wid  = tid >> 5;
    const int wm   = wid >> 2;
    const int wn   = wid & 3;
    const int mblk = blockIdx.y * BM;
    const int nblk = blockIdx.x * BN;

    auto load_stage = [&](int kc, int st){
        const uint32_t sb = sbase + st * STAGE_F16;
        #pragma unroll
        for (int mat = 0; mat < 2; mat++) {
            const unsigned short* gsrc = mat ? B : A;
            int rbase = mat ? nblk : mblk;
            #pragma unroll
            for (int j = 0; j < 4; j++) {
                int id  = tid + j * 256;
                int row = id >> 3;
                int c   = id & 7;
                uint32_t soff = mat * 16384 + row * 128 + ((c ^ (row & 7)) << 4);
                const void* g = gsrc + (size_t)(rbase + row) * 1024 + kc * 64 + c * 8;
                cp16(sb + soff, g);
            }
        }
        asm volatile("cp.async.commit_group;" ::: "memory");
    };

    float acc[4][4][4];
    #pragma unroll
    for (int i = 0; i < 4; i++)
        #pragma unroll
        for (int j = 0; j < 4; j++)
            #pragma unroll
            for (int e = 0; e < 4; e++) acc[i][j][e] = 0.f;

    load_stage(0, 0);
    load_stage(1, 1);

    for (int kc = 0; kc < 16; kc++) {
        if (kc < 15) asm volatile("cp.async.wait_group 1;" ::: "memory");
        else         asm volatile("cp.async.wait_group 0;" ::: "memory");
        __syncthreads();

        const uint32_t sb = sbase + (kc % NSTAGE) * STAGE_F16;
        const uint32_t sA = sb, sB = sb + 16384;

        #pragma unroll
        for (int s = 0; s < 4; s++) {
            uint32_t af[4][4];
            {
                int r = wm * 64 + (lane & 15);
                int c = 2 * s + (lane >> 4);
                #pragma unroll
                for (int mt = 0; mt < 4; mt++) {
                    int rr = r + mt * 16;
                    ldsm_x4(af[mt], sA + rr * 128 + ((c ^ (rr & 7)) << 4));
                }
            }
            uint32_t bf[4][2];
            {
                int r = wn * 32 + (lane & 15);
                int c = 2 * s + (lane >> 4);
                #pragma unroll
                for (int p = 0; p < 2; p++) {
                    int rr = r + p * 16;
                    uint32_t t4[4];
                    ldsm_x4(t4, sB + rr * 128 + ((c ^ (rr & 7)) << 4));
                    bf[p*2+0][0] = t4[0]; bf[p*2+0][1] = t4[2];
                    bf[p*2+1][0] = t4[1]; bf[p*2+1][1] = t4[3];
                }
            }
            #pragma unroll
            for (int mt = 0; mt < 4; mt++)
                #pragma unroll
                for (int nt = 0; nt < 4; nt++)
                    mma_f16(acc[mt][nt], af[mt], bf[nt][0], bf[nt][1]);
        }
        __syncthreads();
        if (kc + 2 < 16) load_stage(kc + 2, (kc + 2) % NSTAGE);
    }

    // epilogue
    const int bi = nblk >> 10;          // mode 0: 0=q 1=k 2=v
    float rsum[4][2];
    #pragma unroll
    for (int mt = 0; mt < 4; mt++) { rsum[mt][0] = 0.f; rsum[mt][1] = 0.f; }

    #pragma unroll
    for (int mt = 0; mt < 4; mt++) {
        #pragma unroll
        for (int nt = 0; nt < 4; nt++) {
            int m0  = mblk + wm * 64 + mt * 16 + (lane >> 2);
            int n_g = nblk + wn * 32 + nt * 8 + 2 * (lane & 3);
            float b0 = bias[n_g], b1 = bias[n_g + 1];
            float vx0 = acc[mt][nt][0] + b0, vy0 = acc[mt][nt][1] + b1;
            float vx1 = acc[mt][nt][2] + b0, vy1 = acc[mt][nt][3] + b1;
            if (mode == 0) {
                uint32_t* dst = (uint32_t*)((bi == 0) ? out0 : (bi == 1) ? out1 : out2);
                int nl = n_g & 1023;
                dst[(size_t)m0 * 512 + (nl >> 1)]       = pack_h2(vx0, vy0);
                dst[(size_t)(m0 + 8) * 512 + (nl >> 1)] = pack_h2(vx1, vy1);
                if (bi < 2) {
                    rsum[mt][0] += vx0 * vx0 + vy0 * vy0;
                    rsum[mt][1] += vx1 * vx1 + vy1 * vy1;
                }
            } else {
                float* dst = (float*)out0;
                *(float2*)&dst[(size_t)m0 * 1024 + n_g]       = make_float2(vx0, vy0);
                *(float2*)&dst[(size_t)(m0 + 8) * 1024 + n_g] = make_float2(vx1, vy1);
            }
        }
    }
    if (mode == 0 && bi < 2) {
        float* ssq = bi ? ssq_k : ssq_q;
        #pragma unroll
        for (int mt = 0; mt < 4; mt++) {
            #pragma unroll
            for (int h = 0; h < 2; h++) {
                float v = rsum[mt][h];
                v += __shfl_xor_sync(0xffffffffu, v, 1);
                v += __shfl_xor_sync(0xffffffffu, v, 2);
                if ((lane & 3) == 0) {
                    int row = mblk + wm * 64 + mt * 16 + (lane >> 2) + h * 8;
                    atomicAdd(&ssq[row], v);
                }
            }
        }
    }
}

// ---------------- small-world attention ---------------------------------------
// One warp per (token, head-pair). Lane group (0-15 / 16-31) = one head,
// lane owns 4 dims (uint2 = 4 halves). 4-shfl 16-lane reduction.
__global__ __launch_bounds__(256)
void attn_kernel(const unsigned short* __restrict__ q16,
                 const unsigned short* __restrict__ k16,
                 const unsigned short* __restrict__ v16,
                 const float* __restrict__ qn, const float* __restrict__ kn,
                 const float* __restrict__ eb, const int* __restrict__ p_nf,
                 const float* __restrict__ ssq_q, const float* __restrict__ ssq_k,
                 uint32_t* __restrict__ af16)
{
    const int gwarp = (blockIdx.x * blockDim.x + threadIdx.x) >> 5;
    const int lane  = threadIdx.x & 31;
    const int token = gwarp >> 3;
    const int hp    = gwarp & 7;
    const int head  = hp * 2 + (lane >> 4);
    const int sub   = lane & 15;
    const int dim0  = head * D_DIM + sub * 4;

    int iv = *p_nf;
    int T;
    if (iv >= 1 && iv <= L_TOK && (L_TOK % iv) == 0) T = iv;
    else T = (int)__int_as_float(iv);
    const int S = L_TOK / T;

    const int t = token / S;
    const int s = token - t * S;

    float rq = rsqrtf(ssq_q[token] * (1.0f / INNER) + 1e-6f);
    float4 qw = *(const float4*)&qn[dim0];
    float4 kw = *(const float4*)&kn[dim0];
    uint2 qp = *(const uint2*)&q16[(size_t)token * 1024 + dim0];
    float2 qa = unpack_h2(qp.x), qb = unpack_h2(qp.y);
    float pre = 0.125f * rq;
    qa.x *= qw.x * kw.x * pre;  qa.y *= qw.y * kw.y * pre;
    qb.x *= qw.z * kw.z * pre;  qb.y *= qw.w * kw.w * pre;

    float sc[NSHIFT];
    uint2 vp[NSHIFT];
    #pragma unroll
    for (int n = 0; n < NSHIFT; n++) {
        int sft = c_shift[n];
        int tok2;
        if (n < 12) {
            int s2 = s + sft;
            while (s2 < 0)  s2 += S;
            while (s2 >= S) s2 -= S;
            tok2 = t * S + s2;
        } else {
            int t2 = t + sft;
            while (t2 < 0)  t2 += T;
            while (t2 >= T) t2 -= T;
            tok2 = t2 * S + s;
        }
        size_t nb = (size_t)tok2 * 1024 + dim0;
        uint2 kp = *(const uint2*)&k16[nb];
        float2 k0 = unpack_h2(kp.x), k1 = unpack_h2(kp.y);
        float p = qa.x * k0.x + qa.y * k0.y + qb.x * k1.x + qb.y * k1.y;
        p += __shfl_xor_sync(0xffffffffu, p, 8);
        p += __shfl_xor_sync(0xffffffffu, p, 4);
        p += __shfl_xor_sync(0xffffffffu, p, 2);
        p += __shfl_xor_sync(0xffffffffu, p, 1);
        float rk = rsqrtf(ssq_k[tok2] * (1.0f / INNER) + 1e-6f);
        sc[n] = p * rk + eb[head * NSHIFT + n];
        vp[n] = *(const uint2*)&v16[nb];
    }

    float m = sc[0];
    #pragma unroll
    for (int n = 1; n < NSHIFT; n++) m = fmaxf(m, sc[n]);
    float sum = 0.f;
    #pragma unroll
    for (int n = 0; n < NSHIFT; n++) { sc[n] = __expf(sc[n] - m); sum += sc[n]; }
    float inv = 1.0f / sum;

    float a0 = 0.f, a1 = 0.f, a2 = 0.f, a3 = 0.f;
    #pragma unroll
    for (int n = 0; n < NSHIFT; n++) {
        float w = sc[n] * inv;
        float2 v0 = unpack_h2(vp[n].x), v1 = unpack_h2(vp[n].y);
        a0 += w * v0.x; a1 += w * v0.y;
        a2 += w * v1.x; a3 += w * v1.y;
    }

    uint2 o = make_uint2(pack_h2(a0, a1), pack_h2(a2, a3));
    *(uint2*)&af16[(size_t)token * 512 + head * 32 + sub * 2] = o;
}

// ---------------------------------------------------------------------------
extern "C" void kernel_launch(void* const* d_in, const int* in_sizes, int n_in,
                              void* d_out, int out_size)
{
    const float* x  = (const float*)d_in[0];
    const float* Wq = (const float*)d_in[1];
    const float* bq = (const float*)d_in[2];
    const float* Wk = (const float*)d_in[3];
    const float* bk = (const float*)d_in[4];
    const float* Wv = (const float*)d_in[5];
    const float* bv = (const float*)d_in[6];
    const float* qn = (const float*)d_in[7];
    const float* kn = (const float*)d_in[8];
    const float* eb = (const float*)d_in[9];
    const float* Wo = (const float*)d_in[10];
    const float* bo = (const float*)d_in[11];
    const int*   nf = (const int*)d_in[12];
    float* out = (float*)d_out;

    unsigned short *xf16,*af16,*wqkv,*wo16,*q16,*k16,*v16;
    float *bqkv,*ssq_q,*ssq_k;
    cudaGetSymbolAddress((void**)&xf16, g_xf16);
    cudaGetSymbolAddress((void**)&af16, g_af16);
    cudaGetSymbolAddress((void**)&wqkv, g_wqkv16);
    cudaGetSymbolAddress((void**)&wo16, g_wo16);
    cudaGetSymbolAddress((void**)&q16, g_q16);
    cudaGetSymbolAddress((void**)&k16, g_k16);
    cudaGetSymbolAddress((void**)&v16, g_v16);
    cudaGetSymbolAddress((void**)&bqkv, g_bqkv);
    cudaGetSymbolAddress((void**)&ssq_q, g_ssq_q);
    cudaGetSymbolAddress((void**)&ssq_k, g_ssq_k);

    cudaFuncSetAttribute(gemm_f16, cudaFuncAttributeMaxDynamicSharedMemorySize, SMEM_F16);

    init_misc<<<76, 256>>>(bq, bk, bv, bqkv, ssq_q, ssq_k);
    conv_x<<<8192, 256>>>(x, (uint32_t*)xf16);
    conv_w_all<<<dim3(32, 32, 4), 256>>>(Wq, Wk, Wv, Wo,
                                         (uint32_t*)wqkv, (uint32_t*)wo16);

    // fused QKV projection (N = 3072), fp16 outputs + per-row sumsq for q,k
    gemm_f16<<<dim3(24, 64), 256, SMEM_F16>>>(xf16, wqkv, bqkv,
                                              q16, k16, v16, ssq_q, ssq_k, 0);

    // attention: 8192 tokens x 8 head-pairs = 65536 warps
    attn_kernel<<<(L_TOK * 8) / 8, 256>>>(q16, k16, v16, qn, kn, eb, nf,
                                          ssq_q, ssq_k, (uint32_t*)af16);

    // output projection (fp32 out)
    gemm_f16<<<dim3(8, 64), 256, SMEM_F16>>>(af16, wo16, bo,
                                             out, out, out, nullptr, nullptr, 1);
}